// round 4
// baseline (speedup 1.0000x reference)
#include <cuda_runtime.h>
#include <cuda_bf16.h>
#include <math.h>

// ---------------- problem constants ----------------
#define Bq   2
#define Sq   2048
#define Dq   1024
#define Hq   16
#define HDq  64
#define Mq   (Bq*Sq)          // 4096
#define NEGV (-10000.0f)

// ---------------- scratch (device globals; no allocation allowed) ----------
__device__ float g_qh[Bq*Hq*Sq*HDq];   // [b][h][s][hd]
__device__ float g_kh[Bq*Hq*Sq*HDq];
__device__ float g_vh[Bq*Hq*Sq*HDq];
__device__ float g_ctx[Bq*Sq*Dq];      // merged [b*S+s][h*64+hd]

// =====================================================================
// GEMM: C = A (MxK row-major) * B^T (B is NxK row-major), M=4096 N=1024 K=1024
// 64x64 tile, BK=16, 256 threads, 4x4 microtile.
// mode 0: plain row-major C[m*N+n]
// mode 1: head-split write to [( (m/S)*H + n/64 )*S + m%S]*64 + n%64
// =====================================================================
__global__ __launch_bounds__(256)
void gemm_abt_kernel(const float* __restrict__ A,
                     const float* __restrict__ Bm,
                     float* __restrict__ C,
                     int mode)
{
    const int Kk = Dq;               // 1024
    const int Nn = Dq;               // 1024
    __shared__ float As[16][65];
    __shared__ float Bs[16][65];

    const int tid = threadIdx.x;
    const int tx = tid & 15;
    const int ty = tid >> 4;
    const int m0 = blockIdx.y * 64;
    const int n0 = blockIdx.x * 64;

    float acc[4][4];
    #pragma unroll
    for (int i = 0; i < 4; i++)
        #pragma unroll
        for (int j = 0; j < 4; j++) acc[i][j] = 0.0f;

    for (int k0 = 0; k0 < Kk; k0 += 16) {
        // load 64x16 A tile and 64x16 B tile (transposed into smem [k][row])
        #pragma unroll
        for (int e = tid; e < 64*16; e += 256) {
            int r = e >> 4;
            int c = e & 15;
            As[c][r] = A[(size_t)(m0 + r) * Kk + k0 + c];
            Bs[c][r] = Bm[(size_t)(n0 + r) * Kk + k0 + c];
        }
        __syncthreads();
        #pragma unroll
        for (int k = 0; k < 16; k++) {
            float a[4], b[4];
            #pragma unroll
            for (int i = 0; i < 4; i++) a[i] = As[k][ty*4 + i];
            #pragma unroll
            for (int j = 0; j < 4; j++) b[j] = Bs[k][tx*4 + j];
            #pragma unroll
            for (int i = 0; i < 4; i++)
                #pragma unroll
                for (int j = 0; j < 4; j++) acc[i][j] += a[i] * b[j];
        }
        __syncthreads();
    }

    #pragma unroll
    for (int i = 0; i < 4; i++) {
        int m = m0 + ty*4 + i;
        #pragma unroll
        for (int j = 0; j < 4; j++) {
            int n = n0 + tx*4 + j;
            if (mode == 0) {
                C[(size_t)m * Nn + n] = acc[i][j];
            } else {
                int bb = m >> 11;          // m / S  (S=2048)
                int ss = m & (Sq - 1);
                int hh = n >> 6;           // n / 64
                int hd = n & 63;
                C[((size_t)(bb*Hq + hh) * Sq + ss) * HDq + hd] = acc[i][j];
            }
        }
    }
}

// =====================================================================
// Flash attention: per block = one (b,h) and one 64-row Q chunk.
// 256 threads (16x16), 4x4 microtiles, online softmax.
// Exact replication of reference masking: causal bias = +(-10000) where
// col>row (if mask_future), then pad replaces score with -10000 where
// attn_mask[key]==0. Tail (fully-future) tiles are skipped ONLY when every
// row's running max > -5000 (i.e., at least one real-valued entry exists).
// =====================================================================
__global__ __launch_bounds__(256)
void attn_kernel(const float* __restrict__ qh,
                 const float* __restrict__ kh,
                 const float* __restrict__ vh,
                 const int*   __restrict__ attn_mask,
                 const int*   __restrict__ mask_future_p,
                 float* __restrict__ ctx)
{
    extern __shared__ float sm[];
    float* Qs = sm;                 // 64*65
    float* Ks = Qs + 64*65;
    float* Vs = Ks + 64*65;
    float* Ps = Vs + 64*65;
    __shared__ int   padm[64];
    __shared__ float wred[8];
    __shared__ int   s_needtail;

    const int bh = blockIdx.y;           // 0..31  (b*H + h)
    const int b  = bh / Hq;
    const int h  = bh % Hq;
    const int qt = blockIdx.x;            // 0..31
    const int qr0 = qt * 64;
    const int tid = threadIdx.x;
    const int tx = tid & 15;
    const int ty = tid >> 4;
    const int mask_future = mask_future_p[0];

    // load Q tile (64 x 64)
    const float* Qg = qh + ((size_t)bh * Sq + qr0) * HDq;
    #pragma unroll
    for (int e = tid; e < 64*64; e += 256) {
        int r = e >> 6, c = e & 63;
        Qs[r*65 + c] = Qg[(size_t)r * HDq + c];
    }

    float m_[4], l_[4], o_[4][4];
    #pragma unroll
    for (int i = 0; i < 4; i++) {
        m_[i] = -1e30f; l_[i] = 0.0f;
        #pragma unroll
        for (int j = 0; j < 4; j++) o_[i][j] = 0.0f;
    }

    const int ntiles = Sq / 64;   // 32
    const int limit = mask_future ? (qt + 1) : ntiles;

    for (int phase = 0; phase < 2; phase++) {
        int t0, t1;
        if (phase == 0) { t0 = 0; t1 = limit; }
        else {
            if (!mask_future || limit >= ntiles) break;
            // do any rows still lack a "real" (non-(-10000)-dominated) max?
            float mymin = fminf(fminf(m_[0], m_[1]), fminf(m_[2], m_[3]));
            #pragma unroll
            for (int off = 16; off > 0; off >>= 1)
                mymin = fminf(mymin, __shfl_xor_sync(0xffffffffu, mymin, off));
            __syncthreads();
            if ((tid & 31) == 0) wred[tid >> 5] = mymin;
            __syncthreads();
            if (tid == 0) {
                float mn = wred[0];
                #pragma unroll
                for (int w = 1; w < 8; w++) mn = fminf(mn, wred[w]);
                s_needtail = (mn < -5000.0f) ? 1 : 0;
            }
            __syncthreads();
            if (!s_needtail) break;
            t0 = limit; t1 = ntiles;
        }

        for (int t = t0; t < t1; t++) {
            const int kv0 = t * 64;
            const float* Kg = kh + ((size_t)bh * Sq + kv0) * HDq;
            const float* Vg = vh + ((size_t)bh * Sq + kv0) * HDq;
            __syncthreads();   // previous tile's P@V must be done before overwrite
            #pragma unroll
            for (int e = tid; e < 64*64; e += 256) {
                int r = e >> 6, c = e & 63;
                Ks[r*65 + c] = Kg[(size_t)r * HDq + c];
                Vs[r*65 + c] = Vg[(size_t)r * HDq + c];
            }
            if (tid < 64) padm[tid] = attn_mask[(size_t)b * Sq + kv0 + tid];
            __syncthreads();

            // scores S = Q @ K^T   (4x4 per thread)
            float cacc[4][4];
            #pragma unroll
            for (int i = 0; i < 4; i++)
                #pragma unroll
                for (int j = 0; j < 4; j++) cacc[i][j] = 0.0f;
            #pragma unroll
            for (int d = 0; d < 64; d++) {
                float a[4], bb[4];
                #pragma unroll
                for (int i = 0; i < 4; i++) a[i]  = Qs[(ty*4 + i)*65 + d];
                #pragma unroll
                for (int j = 0; j < 4; j++) bb[j] = Ks[(tx*4 + j)*65 + d];
                #pragma unroll
                for (int i = 0; i < 4; i++)
                    #pragma unroll
                    for (int j = 0; j < 4; j++) cacc[i][j] += a[i] * bb[j];
            }

            // scale + causal bias + pad replacement (exact reference order)
            #pragma unroll
            for (int i = 0; i < 4; i++) {
                int grow = qr0 + ty*4 + i;
                #pragma unroll
                for (int j = 0; j < 4; j++) {
                    int lcol = tx*4 + j;
                    int gcol = kv0 + lcol;
                    float sv = cacc[i][j] * 0.125f;
                    if (mask_future && (gcol > grow)) sv += NEGV;
                    if (padm[lcol] == 0) sv = NEGV;
                    cacc[i][j] = sv;
                }
            }

            // online softmax (rows owned by the 16 threads sharing ty)
            #pragma unroll
            for (int i = 0; i < 4; i++) {
                float tmax = fmaxf(fmaxf(cacc[i][0], cacc[i][1]),
                                   fmaxf(cacc[i][2], cacc[i][3]));
                #pragma unroll
                for (int off = 8; off > 0; off >>= 1)
                    tmax = fmaxf(tmax, __shfl_xor_sync(0xffffffffu, tmax, off));
                float mnew  = fmaxf(m_[i], tmax);
                float alpha = __expf(m_[i] - mnew);
                float rs = 0.0f;
                #pragma unroll
                for (int j = 0; j < 4; j++) {
                    float p = __expf(cacc[i][j] - mnew);
                    cacc[i][j] = p;
                    rs += p;
                }
                #pragma unroll
                for (int off = 8; off > 0; off >>= 1)
                    rs += __shfl_xor_sync(0xffffffffu, rs, off);
                l_[i] = l_[i] * alpha + rs;
                m_[i] = mnew;
                #pragma unroll
                for (int j = 0; j < 4; j++) o_[i][j] *= alpha;
                #pragma unroll
                for (int j = 0; j < 4; j++)
                    Ps[(ty*4 + i)*65 + tx*4 + j] = cacc[i][j];
            }
            __syncthreads();

            // O += P @ V
            #pragma unroll
            for (int kv = 0; kv < 64; kv++) {
                float p[4], vv[4];
                #pragma unroll
                for (int i = 0; i < 4; i++) p[i]  = Ps[(ty*4 + i)*65 + kv];
                #pragma unroll
                for (int j = 0; j < 4; j++) vv[j] = Vs[kv*65 + tx*4 + j];
                #pragma unroll
                for (int i = 0; i < 4; i++)
                    #pragma unroll
                    for (int j = 0; j < 4; j++) o_[i][j] += p[i] * vv[j];
            }
        }
    }

    // epilogue: normalize and write merged ctx[(b*S+s)*D + h*64 + hd]
    #pragma unroll
    for (int i = 0; i < 4; i++) {
        float inv = 1.0f / l_[i];
        int grow = qr0 + ty*4 + i;
        #pragma unroll
        for (int j = 0; j < 4; j++) {
            ctx[((size_t)b * Sq + grow) * Dq + h*HDq + tx*4 + j] = o_[i][j] * inv;
        }
    }
}

// =====================================================================
// launch
// =====================================================================
extern "C" void kernel_launch(void* const* d_in, const int* in_sizes, int n_in,
                              void* d_out, int out_size)
{
    const float* q   = (const float*)d_in[0];
    const float* k   = (const float*)d_in[1];
    const float* v   = (const float*)d_in[2];
    const int*   am  = (const int*)  d_in[3];
    const float* Wq  = (const float*)d_in[4];
    const float* Wk  = (const float*)d_in[5];
    const float* Wv  = (const float*)d_in[6];
    const float* Wo  = (const float*)d_in[7];
    const int*   mf  = (const int*)  d_in[8];
    float* out = (float*)d_out;

    float *qh, *kh, *vh, *ctx;
    cudaGetSymbolAddress((void**)&qh,  g_qh);
    cudaGetSymbolAddress((void**)&kh,  g_kh);
    cudaGetSymbolAddress((void**)&vh,  g_vh);
    cudaGetSymbolAddress((void**)&ctx, g_ctx);

    dim3 gemm_grid(Dq / 64, Mq / 64);   // (16, 64)
    gemm_abt_kernel<<<gemm_grid, 256>>>(q, Wq, qh, 1);
    gemm_abt_kernel<<<gemm_grid, 256>>>(k, Wk, kh, 1);
    gemm_abt_kernel<<<gemm_grid, 256>>>(v, Wv, vh, 1);

    static int smem_set = 0;
    int attn_smem = 4 * 64 * 65 * (int)sizeof(float);   // 66560 B
    cudaFuncSetAttribute(attn_kernel,
                         cudaFuncAttributeMaxDynamicSharedMemorySize,
                         attn_smem);
    (void)smem_set;

    dim3 attn_grid(Sq / 64, Bq * Hq);   // (32, 32)
    attn_kernel<<<attn_grid, 256, attn_smem>>>(qh, kh, vh, am, mf, ctx);

    gemm_abt_kernel<<<gemm_grid, 256>>>(ctx, Wo, out, 0);
}

// round 5
// speedup vs baseline: 1.5002x; 1.5002x over previous
#include <cuda_runtime.h>
#include <cuda_bf16.h>
#include <math.h>

// ---------------- problem constants ----------------
#define Bq   2
#define Sq   2048
#define Dq   1024
#define Hq   16
#define HDq  64
#define Mq   (Bq*Sq)          // 4096
#define NEGV (-10000.0f)

// ---------------- scratch (device globals; no allocation allowed) ----------
__device__ float g_qh[Bq*Hq*Sq*HDq];   // [b][h][s][hd]
__device__ float g_kh[Bq*Hq*Sq*HDq];
__device__ float g_vh[Bq*Hq*Sq*HDq];
__device__ float g_ctx[Bq*Sq*Dq];      // merged [b*S+s][h*64+hd]

// =====================================================================
// GEMM: C = A (MxK row-major) * B^T (B is NxK row-major)
// M=4096 N=1024 K=1024.  128x128 tile, BK=16, 256 threads, 8x8 microtile,
// double-buffered smem, vectorized LDG/LDS/STG.
// mode 0: plain row-major C[m*N+n]
// mode 1: head-split write to [( (m/S)*H + n/64 )*S + m%S]*64 + n%64
// =====================================================================
#define GSTRIDE 132   // 16B-aligned row stride (132*4B = 33*16B)

__global__ __launch_bounds__(256)
void gemm_abt_kernel(const float* __restrict__ A,
                     const float* __restrict__ Bm,
                     float* __restrict__ C,
                     int mode)
{
    extern __shared__ float gsm[];
    float* As = gsm;                       // [2][16][GSTRIDE]
    float* Bs = gsm + 2 * 16 * GSTRIDE;    // [2][16][GSTRIDE]

    const int tid = threadIdx.x;
    const int tx  = tid & 15;
    const int ty  = tid >> 4;
    const int m0  = blockIdx.y * 128;
    const int n0  = blockIdx.x * 128;

    const int r0 = tid >> 2;      // 0..63
    const int c4 = tid & 3;       // 0..3 (which float4 in the 16-wide k slab)

    const float* Ap0 = A  + (size_t)(m0 + r0)      * Dq + c4 * 4;
    const float* Ap1 = A  + (size_t)(m0 + 64 + r0) * Dq + c4 * 4;
    const float* Bp0 = Bm + (size_t)(n0 + r0)      * Dq + c4 * 4;
    const float* Bp1 = Bm + (size_t)(n0 + 64 + r0) * Dq + c4 * 4;

    float acc[8][8];
    #pragma unroll
    for (int i = 0; i < 8; i++)
        #pragma unroll
        for (int j = 0; j < 8; j++) acc[i][j] = 0.0f;

    float4 ra0, ra1, rb0, rb1;

    // transposed store of one float4 (4 consecutive k's for one row)
    auto stash = [&](float* base, float4 v, int r) {
        float* p = base + (c4 * 4) * GSTRIDE + r;
        p[0]           = v.x;
        p[GSTRIDE]     = v.y;
        p[2 * GSTRIDE] = v.z;
        p[3 * GSTRIDE] = v.w;
    };

    // prologue: tile 0 -> buffer 0
    ra0 = *(const float4*)(Ap0);
    ra1 = *(const float4*)(Ap1);
    rb0 = *(const float4*)(Bp0);
    rb1 = *(const float4*)(Bp1);
    stash(As, ra0, r0);
    stash(As, ra1, 64 + r0);
    stash(Bs, rb0, r0);
    stash(Bs, rb1, 64 + r0);
    __syncthreads();

    const int NKT = Dq / 16;   // 64
    for (int kt = 0; kt < NKT; kt++) {
        const int cur = kt & 1;
        if (kt + 1 < NKT) {
            const int ko = (kt + 1) * 16;
            ra0 = *(const float4*)(Ap0 + ko);
            ra1 = *(const float4*)(Ap1 + ko);
            rb0 = *(const float4*)(Bp0 + ko);
            rb1 = *(const float4*)(Bp1 + ko);
        }

        const float* Ab = As + cur * 16 * GSTRIDE;
        const float* Bb = Bs + cur * 16 * GSTRIDE;
        #pragma unroll
        for (int k = 0; k < 16; k++) {
            float4 a0 = *(const float4*)(Ab + k * GSTRIDE + ty * 4);
            float4 a1 = *(const float4*)(Ab + k * GSTRIDE + 64 + ty * 4);
            float4 b0 = *(const float4*)(Bb + k * GSTRIDE + tx * 4);
            float4 b1 = *(const float4*)(Bb + k * GSTRIDE + 64 + tx * 4);
            float av[8] = {a0.x, a0.y, a0.z, a0.w, a1.x, a1.y, a1.z, a1.w};
            float bv[8] = {b0.x, b0.y, b0.z, b0.w, b1.x, b1.y, b1.z, b1.w};
            #pragma unroll
            for (int i = 0; i < 8; i++)
                #pragma unroll
                for (int j = 0; j < 8; j++) acc[i][j] += av[i] * bv[j];
        }

        if (kt + 1 < NKT) {
            float* Ao = As + (cur ^ 1) * 16 * GSTRIDE;
            float* Bo = Bs + (cur ^ 1) * 16 * GSTRIDE;
            stash(Ao, ra0, r0);
            stash(Ao, ra1, 64 + r0);
            stash(Bo, rb0, r0);
            stash(Bo, rb1, 64 + r0);
        }
        __syncthreads();
    }

    // epilogue
    #pragma unroll
    for (int i = 0; i < 8; i++) {
        const int m = m0 + ((i < 4) ? (ty * 4 + i) : (64 + ty * 4 + (i - 4)));
        #pragma unroll
        for (int jh = 0; jh < 2; jh++) {
            const int n = n0 + jh * 64 + tx * 4;
            float4 v = make_float4(acc[i][jh * 4 + 0], acc[i][jh * 4 + 1],
                                   acc[i][jh * 4 + 2], acc[i][jh * 4 + 3]);
            if (mode == 0) {
                *(float4*)(C + (size_t)m * Dq + n) = v;
            } else {
                const int bb = m >> 11;
                const int ss = m & (Sq - 1);
                const int hh = n >> 6;
                const int hd = n & 63;
                *(float4*)(C + (((size_t)(bb * Hq + hh) * Sq + ss) * HDq + hd)) = v;
            }
        }
    }
}

// =====================================================================
// Flash attention: per block = one (b,h) and one 64-row Q chunk.
// 256 threads (16x16), 4x4 microtiles, online softmax, all-float4 smem.
// Layouts: Qs[d][q], Ks[d][kv]  (transposed, stride AST)
//          Vs[kv][d], Ps[q][kv] (natural,    stride AST)
// Exact reference masking: causal bias += -10000 where col>row (if
// mask_future), then pad REPLACES score with -10000 where attn_mask==0.
// Fully-future tail tiles skipped only when every row already has a
// real-valued max (> -5000); otherwise processed (finite-bias semantics).
// =====================================================================
#define AST 68   // 68*4B = 17*16B -> float4-aligned rows

__global__ __launch_bounds__(256)
void attn_kernel(const float* __restrict__ qh,
                 const float* __restrict__ kh,
                 const float* __restrict__ vh,
                 const int*   __restrict__ attn_mask,
                 const int*   __restrict__ mask_future_p,
                 float* __restrict__ ctx)
{
    extern __shared__ float sm[];
    float* Qs = sm;                 // 64*AST  [d][q]
    float* Ks = Qs + 64 * AST;      // 64*AST  [d][kv]
    float* Vs = Ks + 64 * AST;      // 64*AST  [kv][d]
    float* Ps = Vs + 64 * AST;      // 64*AST  [q][kv]
    __shared__ int   padm[64];
    __shared__ float wred[8];
    __shared__ int   s_needtail;

    const int bh = blockIdx.y;           // b*H + h
    const int b  = bh / Hq;
    const int h  = bh % Hq;
    const int qt = blockIdx.x;
    const int qr0 = qt * 64;
    const int tid = threadIdx.x;
    const int tx = tid & 15;
    const int ty = tid >> 4;
    const int mask_future = mask_future_p[0];

    // load Q tile transposed, fold in the 1/8 scale (power of 2 => exact)
    {
        const float* Qg = qh + ((size_t)bh * Sq + qr0) * HDq;
        #pragma unroll
        for (int e = tid; e < 64 * 16; e += 256) {
            int r = e >> 4, c = e & 15;
            float4 v = *(const float4*)(Qg + (size_t)r * HDq + c * 4);
            float* p = Qs + (c * 4) * AST + r;
            p[0]       = v.x * 0.125f;
            p[AST]     = v.y * 0.125f;
            p[2 * AST] = v.z * 0.125f;
            p[3 * AST] = v.w * 0.125f;
        }
    }

    float m_[4], l_[4], o_[4][4];
    #pragma unroll
    for (int i = 0; i < 4; i++) {
        m_[i] = -1e30f; l_[i] = 0.0f;
        #pragma unroll
        for (int j = 0; j < 4; j++) o_[i][j] = 0.0f;
    }

    const int ntiles = Sq / 64;   // 32
    const int limit = mask_future ? (qt + 1) : ntiles;

    for (int phase = 0; phase < 2; phase++) {
        int t0, t1;
        if (phase == 0) { t0 = 0; t1 = limit; }
        else {
            if (!mask_future || limit >= ntiles) break;
            float mymin = fminf(fminf(m_[0], m_[1]), fminf(m_[2], m_[3]));
            #pragma unroll
            for (int off = 16; off > 0; off >>= 1)
                mymin = fminf(mymin, __shfl_xor_sync(0xffffffffu, mymin, off));
            __syncthreads();
            if ((tid & 31) == 0) wred[tid >> 5] = mymin;
            __syncthreads();
            if (tid == 0) {
                float mn = wred[0];
                #pragma unroll
                for (int w = 1; w < 8; w++) mn = fminf(mn, wred[w]);
                s_needtail = (mn < -5000.0f) ? 1 : 0;
            }
            __syncthreads();
            if (!s_needtail) break;
            t0 = limit; t1 = ntiles;
        }

        for (int t = t0; t < t1; t++) {
            const int kv0 = t * 64;
            const float* Kg = kh + ((size_t)bh * Sq + kv0) * HDq;
            const float* Vg = vh + ((size_t)bh * Sq + kv0) * HDq;
            __syncthreads();   // prior P@V (reads Vs/Ps) done before overwrite
            #pragma unroll
            for (int e = tid; e < 64 * 16; e += 256) {
                int r = e >> 4, c = e & 15;
                float4 kv4 = *(const float4*)(Kg + (size_t)r * HDq + c * 4);
                float* p = Ks + (c * 4) * AST + r;     // transposed
                p[0]       = kv4.x;
                p[AST]     = kv4.y;
                p[2 * AST] = kv4.z;
                p[3 * AST] = kv4.w;
                *(float4*)(Vs + r * AST + c * 4) =      // natural
                    *(const float4*)(Vg + (size_t)r * HDq + c * 4);
            }
            if (tid < 64) padm[tid] = attn_mask[(size_t)b * Sq + kv0 + tid];
            __syncthreads();

            // scores S = (Q*scale) @ K^T : 2 LDS.128 per 16 FMA
            float cacc[4][4];
            #pragma unroll
            for (int i = 0; i < 4; i++)
                #pragma unroll
                for (int j = 0; j < 4; j++) cacc[i][j] = 0.0f;
            #pragma unroll
            for (int d = 0; d < 64; d++) {
                float4 a = *(const float4*)(Qs + d * AST + ty * 4);
                float4 bb = *(const float4*)(Ks + d * AST + tx * 4);
                float av[4] = {a.x, a.y, a.z, a.w};
                float bv[4] = {bb.x, bb.y, bb.z, bb.w};
                #pragma unroll
                for (int i = 0; i < 4; i++)
                    #pragma unroll
                    for (int j = 0; j < 4; j++) cacc[i][j] += av[i] * bv[j];
            }

            // causal bias then pad replacement (exact reference order)
            #pragma unroll
            for (int i = 0; i < 4; i++) {
                int grow = qr0 + ty * 4 + i;
                #pragma unroll
                for (int j = 0; j < 4; j++) {
                    int lcol = tx * 4 + j;
                    int gcol = kv0 + lcol;
                    float sv = cacc[i][j];
                    if (mask_future && (gcol > grow)) sv += NEGV;
                    if (padm[lcol] == 0) sv = NEGV;
                    cacc[i][j] = sv;
                }
            }

            // online softmax (row groups owned by 16 threads sharing ty)
            #pragma unroll
            for (int i = 0; i < 4; i++) {
                float tmax = fmaxf(fmaxf(cacc[i][0], cacc[i][1]),
                                   fmaxf(cacc[i][2], cacc[i][3]));
                #pragma unroll
                for (int off = 8; off > 0; off >>= 1)
                    tmax = fmaxf(tmax, __shfl_xor_sync(0xffffffffu, tmax, off));
                float mnew  = fmaxf(m_[i], tmax);
                float alpha = __expf(m_[i] - mnew);
                float rs = 0.0f;
                #pragma unroll
                for (int j = 0; j < 4; j++) {
                    float p = __expf(cacc[i][j] - mnew);
                    cacc[i][j] = p;
                    rs += p;
                }
                #pragma unroll
                for (int off = 8; off > 0; off >>= 1)
                    rs += __shfl_xor_sync(0xffffffffu, rs, off);
                l_[i] = l_[i] * alpha + rs;
                m_[i] = mnew;
                #pragma unroll
                for (int j = 0; j < 4; j++) o_[i][j] *= alpha;
                *(float4*)(Ps + (ty * 4 + i) * AST + tx * 4) =
                    make_float4(cacc[i][0], cacc[i][1], cacc[i][2], cacc[i][3]);
            }
            __syncthreads();

            // O += P @ V : 8 LDS.128 per 64 FMA
            #pragma unroll
            for (int kv = 0; kv < 64; kv += 4) {
                float4 p4[4], v4[4];
                #pragma unroll
                for (int i = 0; i < 4; i++)
                    p4[i] = *(const float4*)(Ps + (ty * 4 + i) * AST + kv);
                #pragma unroll
                for (int tt = 0; tt < 4; tt++)
                    v4[tt] = *(const float4*)(Vs + (kv + tt) * AST + tx * 4);
                #pragma unroll
                for (int i = 0; i < 4; i++) {
                    float pv[4] = {p4[i].x, p4[i].y, p4[i].z, p4[i].w};
                    #pragma unroll
                    for (int tt = 0; tt < 4; tt++) {
                        o_[i][0] += pv[tt] * v4[tt].x;
                        o_[i][1] += pv[tt] * v4[tt].y;
                        o_[i][2] += pv[tt] * v4[tt].z;
                        o_[i][3] += pv[tt] * v4[tt].w;
                    }
                }
            }
        }
    }

    // epilogue: normalize, write merged ctx[(b*S+s)*D + h*64 + hd]
    #pragma unroll
    for (int i = 0; i < 4; i++) {
        float inv = 1.0f / l_[i];
        int grow = qr0 + ty * 4 + i;
        float4 v = make_float4(o_[i][0] * inv, o_[i][1] * inv,
                               o_[i][2] * inv, o_[i][3] * inv);
        *(float4*)(ctx + ((size_t)b * Sq + grow) * Dq + h * HDq + tx * 4) = v;
    }
}

// =====================================================================
// launch
// =====================================================================
extern "C" void kernel_launch(void* const* d_in, const int* in_sizes, int n_in,
                              void* d_out, int out_size)
{
    const float* q   = (const float*)d_in[0];
    const float* k   = (const float*)d_in[1];
    const float* v   = (const float*)d_in[2];
    const int*   am  = (const int*)  d_in[3];
    const float* Wq  = (const float*)d_in[4];
    const float* Wk  = (const float*)d_in[5];
    const float* Wv  = (const float*)d_in[6];
    const float* Wo  = (const float*)d_in[7];
    const int*   mf  = (const int*)  d_in[8];
    float* out = (float*)d_out;

    float *qh, *kh, *vh, *ctx;
    cudaGetSymbolAddress((void**)&qh,  g_qh);
    cudaGetSymbolAddress((void**)&kh,  g_kh);
    cudaGetSymbolAddress((void**)&vh,  g_vh);
    cudaGetSymbolAddress((void**)&ctx, g_ctx);

    const int gemm_smem = 2 * 2 * 16 * GSTRIDE * (int)sizeof(float);   // 67584
    const int attn_smem = 4 * 64 * AST * (int)sizeof(float);           // 69632
    cudaFuncSetAttribute(gemm_abt_kernel,
                         cudaFuncAttributeMaxDynamicSharedMemorySize, gemm_smem);
    cudaFuncSetAttribute(attn_kernel,
                         cudaFuncAttributeMaxDynamicSharedMemorySize, attn_smem);

    dim3 gemm_grid(Dq / 128, Mq / 128);   // (8, 32) = 256 blocks
    gemm_abt_kernel<<<gemm_grid, 256, gemm_smem>>>(q, Wq, qh, 1);
    gemm_abt_kernel<<<gemm_grid, 256, gemm_smem>>>(k, Wk, kh, 1);
    gemm_abt_kernel<<<gemm_grid, 256, gemm_smem>>>(v, Wv, vh, 1);

    dim3 attn_grid(Sq / 64, Bq * Hq);     // (32, 32)
    attn_kernel<<<attn_grid, 256, attn_smem>>>(qh, kh, vh, am, mf, ctx);

    gemm_abt_kernel<<<gemm_grid, 256, gemm_smem>>>(ctx, Wo, out, 0);
}

// round 7
// speedup vs baseline: 1.6438x; 1.0957x over previous
#include <cuda_runtime.h>
#include <cuda_bf16.h>
#include <math.h>
#include <stdint.h>

// ---------------- problem constants ----------------
#define Bq   2
#define Sq   2048
#define Dq   1024
#define Hq   16
#define HDq  64
#define Mq   (Bq*Sq)          // 4096
#define NEGV (-10000.0f)

// ---------------- scratch (device globals; no allocation allowed) ----------
__device__ float g_qh[Bq*Hq*Sq*HDq];   // [b][h][s][hd]
__device__ float g_kh[Bq*Hq*Sq*HDq];
__device__ float g_vh[Bq*Hq*Sq*HDq];
__device__ float g_ctx[Bq*Sq*Dq];      // merged [b*S+s][h*64+hd]

// bf16 hi/lo copies for tensor-core GEMMs
__device__ __nv_bfloat16 g_q_hi[Mq*Dq],  g_q_lo[Mq*Dq];
__device__ __nv_bfloat16 g_k_hi[Mq*Dq],  g_k_lo[Mq*Dq];
__device__ __nv_bfloat16 g_v_hi[Mq*Dq],  g_v_lo[Mq*Dq];
__device__ __nv_bfloat16 g_c_hi[Mq*Dq],  g_c_lo[Mq*Dq];
__device__ __nv_bfloat16 g_wq_hi[Dq*Dq], g_wq_lo[Dq*Dq];
__device__ __nv_bfloat16 g_wk_hi[Dq*Dq], g_wk_lo[Dq*Dq];
__device__ __nv_bfloat16 g_wv_hi[Dq*Dq], g_wv_lo[Dq*Dq];
__device__ __nv_bfloat16 g_wo_hi[Dq*Dq], g_wo_lo[Dq*Dq];

// =====================================================================
// helpers
// =====================================================================
__device__ __forceinline__ uint32_t smem_u32(const void* p) {
    uint32_t a;
    asm("{ .reg .u64 t; cvta.to.shared.u64 t, %1; cvt.u32.u64 %0, t; }"
        : "=r"(a) : "l"(p));
    return a;
}

__device__ __forceinline__ void ldsm_x4(uint32_t* r, uint32_t addr) {
    asm volatile("ldmatrix.sync.aligned.m8n8.x4.shared.b16 {%0,%1,%2,%3}, [%4];"
                 : "=r"(r[0]), "=r"(r[1]), "=r"(r[2]), "=r"(r[3]) : "r"(addr));
}

__device__ __forceinline__ void mma_bf16(float* c, const uint32_t* a,
                                         const uint32_t* b) {
    asm volatile(
        "mma.sync.aligned.m16n8k16.row.col.f32.bf16.bf16.f32 "
        "{%0,%1,%2,%3}, {%4,%5,%6,%7}, {%8,%9}, {%0,%1,%2,%3};"
        : "+f"(c[0]), "+f"(c[1]), "+f"(c[2]), "+f"(c[3])
        : "r"(a[0]), "r"(a[1]), "r"(a[2]), "r"(a[3]), "r"(b[0]), "r"(b[1]));
}

// =====================================================================
// fp32 -> bf16 hi/lo split, vectorized (exact residual: lo = bf16(x - hi))
// =====================================================================
__global__ __launch_bounds__(256)
void cvt_hilo_kernel(const float* __restrict__ x,
                     __nv_bfloat16* __restrict__ hi,
                     __nv_bfloat16* __restrict__ lo, int n4)
{
    int i = blockIdx.x * blockDim.x + threadIdx.x;
    if (i >= n4) return;
    float4 v = ((const float4*)x)[i];
    __nv_bfloat16 h0 = __float2bfloat16(v.x);
    __nv_bfloat16 h1 = __float2bfloat16(v.y);
    __nv_bfloat16 h2 = __float2bfloat16(v.z);
    __nv_bfloat16 h3 = __float2bfloat16(v.w);
    __nv_bfloat16 l0 = __float2bfloat16(v.x - __bfloat162float(h0));
    __nv_bfloat16 l1 = __float2bfloat16(v.y - __bfloat162float(h1));
    __nv_bfloat16 l2 = __float2bfloat16(v.z - __bfloat162float(h2));
    __nv_bfloat16 l3 = __float2bfloat16(v.w - __bfloat162float(h3));
    uint2 uh = make_uint2(
        (uint32_t)__bfloat16_as_ushort(h0) | ((uint32_t)__bfloat16_as_ushort(h1) << 16),
        (uint32_t)__bfloat16_as_ushort(h2) | ((uint32_t)__bfloat16_as_ushort(h3) << 16));
    uint2 ul = make_uint2(
        (uint32_t)__bfloat16_as_ushort(l0) | ((uint32_t)__bfloat16_as_ushort(l1) << 16),
        (uint32_t)__bfloat16_as_ushort(l2) | ((uint32_t)__bfloat16_as_ushort(l3) << 16));
    ((uint2*)hi)[i] = uh;
    ((uint2*)lo)[i] = ul;
}

// =====================================================================
// Tensor-core GEMM (mma.sync bf16, 3-pass hi/lo):
//   C = A (MxK rm) * B^T (B is NxK rm), M=4096 N=1024 K=1024.
// CTA tile 128(M) x 64(N), BK=32. 8 warps = 4(m) x 2(n), warp tile 32x32.
// smem rows padded to stride 40 bf16 -> conflict-free ldmatrix.
// mode 0: C[m*N+n];  mode 1: head-split [(b*H+h)*S+s]*64+hd.
// =====================================================================
#define ASTRIDE 40
#define SA_HI 0
#define SA_LO (128*ASTRIDE)
#define SB_HI (256*ASTRIDE)
#define SB_LO (256*ASTRIDE + 64*ASTRIDE)
// total smem: 384*40 bf16 = 30720 bytes (< 48KB, no opt-in needed)

__global__ __launch_bounds__(256)
void gemm_mma_kernel(const __nv_bfloat16* __restrict__ Ahi,
                     const __nv_bfloat16* __restrict__ Alo,
                     const __nv_bfloat16* __restrict__ Bhi,
                     const __nv_bfloat16* __restrict__ Blo,
                     float* __restrict__ C, int mode)
{
    __shared__ __nv_bfloat16 sbf[384 * ASTRIDE];
    const uint32_t sbase = smem_u32(sbf);

    const int tid  = threadIdx.x;
    const int wid  = tid >> 5;
    const int lane = tid & 31;
    const int m0 = blockIdx.y * 128;
    const int n0 = blockIdx.x * 64;
    const int wm0 = (wid & 3) * 32;    // warp m offset in tile
    const int wn0 = (wid >> 2) * 32;   // warp n offset in tile

    // lane-dependent ldmatrix row indices (computed once)
    const int mt = lane >> 3;          // matrix index 0..3
    const int rr = lane & 7;
    // A: mat0: rows +0 @k0 | mat1: rows +8 @k0 | mat2: +0 @k8 | mat3: +8 @k8
    const int a_row = rr + 8 * (mt & 1);
    const int a_kof = 8 * (mt >> 1);
    // B: mat0: n +0 @k0 | mat1: n +0 @k8 | mat2: n +8 @k0 | mat3: n +8 @k8
    const int b_row = rr + 8 * (mt >> 1);
    const int b_kof = 8 * (mt & 1);

    float acc[2][4][4];
    #pragma unroll
    for (int i = 0; i < 2; i++)
        #pragma unroll
        for (int j = 0; j < 4; j++)
            #pragma unroll
            for (int e = 0; e < 4; e++) acc[i][j][e] = 0.0f;

    for (int ch = 0; ch < 32; ch++) {
        const int k0g = ch * 32;
        __syncthreads();
        // A tile 128x32 (hi+lo): 2 uint4 per thread per buffer
        #pragma unroll
        for (int j = 0; j < 2; j++) {
            const int idx = tid + j * 256;
            const int r = idx >> 2, kc = idx & 3;
            const size_t go = (size_t)(m0 + r) * Dq + k0g + kc * 8;
            *(uint4*)(sbf + SA_HI + r * ASTRIDE + kc * 8) = *(const uint4*)(Ahi + go);
            *(uint4*)(sbf + SA_LO + r * ASTRIDE + kc * 8) = *(const uint4*)(Alo + go);
        }
        // B tile 64x32 (hi+lo): 1 uint4 per thread per buffer
        {
            const int r = tid >> 2, kc = tid & 3;
            const size_t go = (size_t)(n0 + r) * Dq + k0g + kc * 8;
            *(uint4*)(sbf + SB_HI + r * ASTRIDE + kc * 8) = *(const uint4*)(Bhi + go);
            *(uint4*)(sbf + SB_LO + r * ASTRIDE + kc * 8) = *(const uint4*)(Blo + go);
        }
        __syncthreads();

        #pragma unroll
        for (int ks = 0; ks < 32; ks += 16) {
            uint32_t ahi[2][4], alo[2][4], bhi[2][4], blo[2][4];
            #pragma unroll
            for (int mf = 0; mf < 2; mf++) {
                const int row = wm0 + mf * 16 + a_row;
                const int kk  = ks + a_kof;
                ldsm_x4(ahi[mf], sbase + (uint32_t)(SA_HI + row * ASTRIDE + kk) * 2);
                ldsm_x4(alo[mf], sbase + (uint32_t)(SA_LO + row * ASTRIDE + kk) * 2);
            }
            #pragma unroll
            for (int p = 0; p < 2; p++) {
                const int row = wn0 + p * 16 + b_row;
                const int kk  = ks + b_kof;
                ldsm_x4(bhi[p], sbase + (uint32_t)(SB_HI + row * ASTRIDE + kk) * 2);
                ldsm_x4(blo[p], sbase + (uint32_t)(SB_LO + row * ASTRIDE + kk) * 2);
            }
            #pragma unroll
            for (int mf = 0; mf < 2; mf++)
                #pragma unroll
                for (int nf = 0; nf < 4; nf++) {
                    const uint32_t* bh = &bhi[nf >> 1][(nf & 1) * 2];
                    const uint32_t* bl = &blo[nf >> 1][(nf & 1) * 2];
                    mma_bf16(acc[mf][nf], ahi[mf], bh);
                    mma_bf16(acc[mf][nf], ahi[mf], bl);
                    mma_bf16(acc[mf][nf], alo[mf], bh);
                }
        }
    }

    // epilogue: m16n8 accum layout: c0,c1 @(g, c..c+1), c2,c3 @(g+8, c..c+1)
    const int g  = lane >> 2;
    const int cc = (lane & 3) * 2;
    #pragma unroll
    for (int mf = 0; mf < 2; mf++)
        #pragma unroll
        for (int nf = 0; nf < 4; nf++) {
            const int mA = m0 + wm0 + mf * 16 + g;
            const int nA = n0 + wn0 + nf * 8 + cc;
            #pragma unroll
            for (int half = 0; half < 2; half++) {
                const int m = mA + half * 8;
                float2 v = make_float2(acc[mf][nf][half * 2],
                                       acc[mf][nf][half * 2 + 1]);
                if (mode == 0) {
                    *(float2*)(C + (size_t)m * Dq + nA) = v;
                } else {
                    const int bb = m >> 11;
                    const int ss = m & (Sq - 1);
                    const int hh = nA >> 6;
                    const int hd = nA & 63;
                    *(float2*)(C + (((size_t)(bb * Hq + hh) * Sq + ss) * HDq + hd)) = v;
                }
            }
        }
}

// =====================================================================
// Flash attention: per block = one (b,h) and one 128-row Q chunk.
// 128 threads (16 ty x 8 tx), 8x8 microtile -> 1 smem-byte/FMA.
// KV tiles of 64. Online softmax. Exact reference masking semantics:
// causal bias += -10000 where col>row (if mask_future), then pad REPLACES
// score with -10000 where attn_mask==0. Fully-future tail tiles processed
// only when some row's running max is still < -5000.
// =====================================================================
#define QST 132   // Qs row stride (floats), 16B aligned
#define KST 68    // Ks/Vs/Ps row stride

__global__ __launch_bounds__(128)
void attn_kernel(const float* __restrict__ qh,
                 const float* __restrict__ kh,
                 const float* __restrict__ vh,
                 const int*   __restrict__ attn_mask,
                 const int*   __restrict__ mask_future_p,
                 float* __restrict__ ctx)
{
    extern __shared__ float sm[];
    float* Qs = sm;                    // [d=64][q=128] stride QST
    float* Ks = Qs + 64 * QST;         // [d=64][kv=64] stride KST
    float* Vs = Ks + 64 * KST;         // [kv=64][d=64] stride KST
    float* Ps = Vs + 64 * KST;         // [q=128][kv=64] stride KST
    __shared__ int   padm[64];
    __shared__ float wred[4];
    __shared__ int   s_needtail;

    const int bh = blockIdx.y;         // b*H + h
    const int b  = bh / Hq;
    const int h  = bh % Hq;
    const int qb = blockIdx.x;         // 0..15 (128-row Q blocks)
    const int qr0 = qb * 128;
    const int tid = threadIdx.x;
    const int tx = tid & 7;            // 8 col groups
    const int ty = tid >> 3;           // 16 row groups
    const int mask_future = mask_future_p[0];

    // Q tile (128 x 64) -> transposed [d][q], fold 1/8 scale (exact pow2)
    {
        const float* Qg = qh + ((size_t)bh * Sq + qr0) * HDq;
        for (int e = tid; e < 128 * 16; e += 128) {
            const int r = e >> 4, c = e & 15;
            float4 v = *(const float4*)(Qg + (size_t)r * HDq + c * 4);
            float* p = Qs + (c * 4) * QST + r;
            p[0]       = v.x * 0.125f;
            p[QST]     = v.y * 0.125f;
            p[2 * QST] = v.z * 0.125f;
            p[3 * QST] = v.w * 0.125f;
        }
    }

    float m_[8], l_[8], o_[8][8];
    #pragma unroll
    for (int i = 0; i < 8; i++) {
        m_[i] = -1e30f; l_[i] = 0.0f;
        #pragma unroll
        for (int j = 0; j < 8; j++) o_[i][j] = 0.0f;
    }

    const int ntiles = Sq / 64;                    // 32
    const int limit = mask_future ? (2 * qb + 2) : ntiles;

    for (int phase = 0; phase < 2; phase++) {
        int t0, t1;
        if (phase == 0) { t0 = 0; t1 = limit; }
        else {
            if (!mask_future || limit >= ntiles) break;
            float mymin = m_[0];
            #pragma unroll
            for (int i = 1; i < 8; i++) mymin = fminf(mymin, m_[i]);
            #pragma unroll
            for (int off = 16; off > 0; off >>= 1)
                mymin = fminf(mymin, __shfl_xor_sync(0xffffffffu, mymin, off));
            __syncthreads();
            if ((tid & 31) == 0) wred[tid >> 5] = mymin;
            __syncthreads();
            if (tid == 0) {
                float mn = fminf(fminf(wred[0], wred[1]), fminf(wred[2], wred[3]));
                s_needtail = (mn < -5000.0f) ? 1 : 0;
            }
            __syncthreads();
            if (!s_needtail) break;
            t0 = limit; t1 = ntiles;
        }

        for (int t = t0; t < t1; t++) {
            const int kv0 = t * 64;
            const float* Kg = kh + ((size_t)bh * Sq + kv0) * HDq;
            const float* Vg = vh + ((size_t)bh * Sq + kv0) * HDq;
            __syncthreads();   // prior P@V done before overwriting Ks/Vs/Ps
            for (int e = tid; e < 64 * 16; e += 128) {
                const int r = e >> 4, c = e & 15;
                float4 kv4 = *(const float4*)(Kg + (size_t)r * HDq + c * 4);
                float* p = Ks + (c * 4) * KST + r;    // transposed
                p[0]       = kv4.x;
                p[KST]     = kv4.y;
                p[2 * KST] = kv4.z;
                p[3 * KST] = kv4.w;
                *(float4*)(Vs + r * KST + c * 4) =    // natural
                    *(const float4*)(Vg + (size_t)r * HDq + c * 4);
            }
            if (tid < 64) padm[tid] = attn_mask[(size_t)b * Sq + kv0 + tid];
            __syncthreads();

            // S = (Q*scale) @ K^T : 8x8, 4 LDS.128 per 64 FMA
            float cacc[8][8];
            #pragma unroll
            for (int i = 0; i < 8; i++)
                #pragma unroll
                for (int j = 0; j < 8; j++) cacc[i][j] = 0.0f;
            for (int d = 0; d < 64; d++) {
                float4 a0 = *(const float4*)(Qs + d * QST + ty * 8);
                float4 a1 = *(const float4*)(Qs + d * QST + ty * 8 + 4);
                float4 b0 = *(const float4*)(Ks + d * KST + tx * 8);
                float4 b1 = *(const float4*)(Ks + d * KST + tx * 8 + 4);
                float av[8] = {a0.x, a0.y, a0.z, a0.w, a1.x, a1.y, a1.z, a1.w};
                float bv[8] = {b0.x, b0.y, b0.z, b0.w, b1.x, b1.y, b1.z, b1.w};
                #pragma unroll
                for (int i = 0; i < 8; i++)
                    #pragma unroll
                    for (int j = 0; j < 8; j++) cacc[i][j] += av[i] * bv[j];
            }

            // causal bias then pad replacement (exact reference order)
            #pragma unroll
            for (int i = 0; i < 8; i++) {
                const int grow = qr0 + ty * 8 + i;
                #pragma unroll
                for (int j = 0; j < 8; j++) {
                    const int lcol = tx * 8 + j;
                    const int gcol = kv0 + lcol;
                    float sv = cacc[i][j];
                    if (mask_future && (gcol > grow)) sv += NEGV;
                    if (padm[lcol] == 0) sv = NEGV;
                    cacc[i][j] = sv;
                }
            }

            // online softmax: each row spread over 8 tx lanes (shfl 1,2,4)
            #pragma unroll
            for (int i = 0; i < 8; i++) {
                float tmax = cacc[i][0];
                #pragma unroll
                for (int j = 1; j < 8; j++) tmax = fmaxf(tmax, cacc[i][j]);
                #pragma unroll
                for (int off = 4; off > 0; off >>= 1)
                    tmax = fmaxf(tmax, __shfl_xor_sync(0xffffffffu, tmax, off));
                const float mnew  = fmaxf(m_[i], tmax);
                const float alpha = __expf(m_[i] - mnew);
                float rs = 0.0f;
                #pragma unroll
                for (int j = 0; j < 8; j++) {
                    const float p = __expf(cacc[i][j] - mnew);
                    cacc[i][j] = p;
                    rs += p;
                }
                #pragma unroll
                for (int off = 4; off > 0; off >>= 1)
                    rs += __shfl_xor_sync(0xffffffffu, rs, off);
                l_[i] = l_[i] * alpha + rs;
                m_[i] = mnew;
                #pragma unroll
                for (int j = 0; j < 8; j++) o_[i][j] *= alpha;
                *(float4*)(Ps + (ty * 8 + i) * KST + tx * 8) =
                    make_float4(cacc[i][0], cacc[i][1], cacc[i][2], cacc[i][3]);
                *(float4*)(Ps + (ty * 8 + i) * KST + tx * 8 + 4) =
                    make_float4(cacc[i][4], cacc[i][5], cacc[i][6], cacc[i][7]);
            }
            __syncthreads();

            // O += P @ V : 16 LDS.128 per 256 FMA
            for (int kv = 0; kv < 64; kv += 4) {
                float4 p4[8];
                #pragma unroll
                for (int i = 0; i < 8; i++)
                    p4[i] = *(const float4*)(Ps + (ty * 8 + i) * KST + kv);
                float4 va[4], vb[4];
                #pragma unroll
                for (int tt = 0; tt < 4; tt++) {
                    va[tt] = *(const float4*)(Vs + (kv + tt) * KST + tx * 8);
                    vb[tt] = *(const float4*)(Vs + (kv + tt) * KST + tx * 8 + 4);
                }
                #pragma unroll
                for (int i = 0; i < 8; i++) {
                    const float pv[4] = {p4[i].x, p4[i].y, p4[i].z, p4[i].w};
                    #pragma unroll
                    for (int tt = 0; tt < 4; tt++) {
                        o_[i][0] += pv[tt] * va[tt].x;
                        o_[i][1] += pv[tt] * va[tt].y;
                        o_[i][2] += pv[tt] * va[tt].z;
                        o_[i][3] += pv[tt] * va[tt].w;
                        o_[i][4] += pv[tt] * vb[tt].x;
                        o_[i][5] += pv[tt] * vb[tt].y;
                        o_[i][6] += pv[tt] * vb[tt].z;
                        o_[i][7] += pv[tt] * vb[tt].w;
                    }
                }
            }
        }
    }

    // epilogue: normalize, write merged ctx[(b*S+s)*D + h*64 + hd]
    #pragma unroll
    for (int i = 0; i < 8; i++) {
        const float inv = 1.0f / l_[i];
        const int grow = qr0 + ty * 8 + i;
        float* dst = ctx + ((size_t)b * Sq + grow) * Dq + h * HDq + tx * 8;
        *(float4*)(dst) = make_float4(o_[i][0] * inv, o_[i][1] * inv,
                                      o_[i][2] * inv, o_[i][3] * inv);
        *(float4*)(dst + 4) = make_float4(o_[i][4] * inv, o_[i][5] * inv,
                                          o_[i][6] * inv, o_[i][7] * inv);
    }
}

// =====================================================================
// launch
// =====================================================================
extern "C" void kernel_launch(void* const* d_in, const int* in_sizes, int n_in,
                              void* d_out, int out_size)
{
    const float* q   = (const float*)d_in[0];
    const float* k   = (const float*)d_in[1];
    const float* v   = (const float*)d_in[2];
    const int*   am  = (const int*)  d_in[3];
    const float* Wq  = (const float*)d_in[4];
    const float* Wk  = (const float*)d_in[5];
    const float* Wv  = (const float*)d_in[6];
    const float* Wo  = (const float*)d_in[7];
    const int*   mf  = (const int*)  d_in[8];
    float* out = (float*)d_out;

    float *qh, *kh, *vh, *ctx;
    cudaGetSymbolAddress((void**)&qh,  g_qh);
    cudaGetSymbolAddress((void**)&kh,  g_kh);
    cudaGetSymbolAddress((void**)&vh,  g_vh);
    cudaGetSymbolAddress((void**)&ctx, g_ctx);

    __nv_bfloat16 *qhi, *qlo, *khi, *klo, *vhi, *vlo, *chi, *clo;
    __nv_bfloat16 *wqhi, *wqlo, *wkhi, *wklo, *wvhi, *wvlo, *wohi, *wolo;
    cudaGetSymbolAddress((void**)&qhi,  g_q_hi);  cudaGetSymbolAddress((void**)&qlo,  g_q_lo);
    cudaGetSymbolAddress((void**)&khi,  g_k_hi);  cudaGetSymbolAddress((void**)&klo,  g_k_lo);
    cudaGetSymbolAddress((void**)&vhi,  g_v_hi);  cudaGetSymbolAddress((void**)&vlo,  g_v_lo);
    cudaGetSymbolAddress((void**)&chi,  g_c_hi);  cudaGetSymbolAddress((void**)&clo,  g_c_lo);
    cudaGetSymbolAddress((void**)&wqhi, g_wq_hi); cudaGetSymbolAddress((void**)&wqlo, g_wq_lo);
    cudaGetSymbolAddress((void**)&wkhi, g_wk_hi); cudaGetSymbolAddress((void**)&wklo, g_wk_lo);
    cudaGetSymbolAddress((void**)&wvhi, g_wv_hi); cudaGetSymbolAddress((void**)&wvlo, g_wv_lo);
    cudaGetSymbolAddress((void**)&wohi, g_wo_hi); cudaGetSymbolAddress((void**)&wolo, g_wo_lo);

    const int attn_smem =
        (64 * QST + 64 * KST + 64 * KST + 128 * KST) * (int)sizeof(float);
    cudaFuncSetAttribute(attn_kernel,
                         cudaFuncAttributeMaxDynamicSharedMemorySize, attn_smem);

    // --- hi/lo conversions (inputs + weights) ---
    const int nIn4 = Mq * Dq / 4;   // 1048576
    const int nW4  = Dq * Dq / 4;   // 262144
    cvt_hilo_kernel<<<nIn4 / 256, 256>>>(q,  qhi,  qlo,  nIn4);
    cvt_hilo_kernel<<<nIn4 / 256, 256>>>(k,  khi,  klo,  nIn4);
    cvt_hilo_kernel<<<nIn4 / 256, 256>>>(v,  vhi,  vlo,  nIn4);
    cvt_hilo_kernel<<<nW4 / 256,  256>>>(Wq, wqhi, wqlo, nW4);
    cvt_hilo_kernel<<<nW4 / 256,  256>>>(Wk, wkhi, wklo, nW4);
    cvt_hilo_kernel<<<nW4 / 256,  256>>>(Wv, wvhi, wvlo, nW4);
    cvt_hilo_kernel<<<nW4 / 256,  256>>>(Wo, wohi, wolo, nW4);

    // --- projections (tensor cores) ---
    dim3 gemm_grid(Dq / 64, Mq / 128);   // (16, 32) = 512 CTAs
    gemm_mma_kernel<<<gemm_grid, 256>>>(qhi, qlo, wqhi, wqlo, qh, 1);
    gemm_mma_kernel<<<gemm_grid, 256>>>(khi, klo, wkhi, wklo, kh, 1);
    gemm_mma_kernel<<<gemm_grid, 256>>>(vhi, vlo, wvhi, wvlo, vh, 1);

    // --- attention ---
    dim3 attn_grid(Sq / 128, Bq * Hq);   // (16, 32) = 512 CTAs
    attn_kernel<<<attn_grid, 128, attn_smem>>>(qh, kh, vh, am, mf, ctx);

    // --- output projection ---
    cvt_hilo_kernel<<<nIn4 / 256, 256>>>(ctx, chi, clo, nIn4);
    gemm_mma_kernel<<<gemm_grid, 256>>>(chi, clo, wohi, wolo, out, 0);
}

// round 9
// speedup vs baseline: 1.8550x; 1.1285x over previous
#include <cuda_runtime.h>
#include <cuda_bf16.h>
#include <math.h>
#include <stdint.h>

// ---------------- problem constants ----------------
#define Bq   2
#define Sq   2048
#define Dq   1024
#define Hq   16
#define HDq  64
#define Mq   (Bq*Sq)          // 4096
#define NEGV (-10000.0f)

// ---------------- scratch (device globals; no allocation allowed) ----------
__device__ float g_qh[Bq*Hq*Sq*HDq];   // [b][h][s][hd]
__device__ float g_kh[Bq*Hq*Sq*HDq];
__device__ float g_vh[Bq*Hq*Sq*HDq];
__device__ float g_ctx[Bq*Sq*Dq];      // merged [b*S+s][h*64+hd]

// bf16 hi/lo copies for tensor-core GEMMs
__device__ __nv_bfloat16 g_q_hi[Mq*Dq],  g_q_lo[Mq*Dq];
__device__ __nv_bfloat16 g_k_hi[Mq*Dq],  g_k_lo[Mq*Dq];
__device__ __nv_bfloat16 g_v_hi[Mq*Dq],  g_v_lo[Mq*Dq];
__device__ __nv_bfloat16 g_c_hi[Mq*Dq],  g_c_lo[Mq*Dq];
__device__ __nv_bfloat16 g_wq_hi[Dq*Dq], g_wq_lo[Dq*Dq];
__device__ __nv_bfloat16 g_wk_hi[Dq*Dq], g_wk_lo[Dq*Dq];
__device__ __nv_bfloat16 g_wv_hi[Dq*Dq], g_wv_lo[Dq*Dq];
__device__ __nv_bfloat16 g_wo_hi[Dq*Dq], g_wo_lo[Dq*Dq];

// =====================================================================
// helpers
// =====================================================================
__device__ __forceinline__ uint32_t smem_u32(const void* p) {
    uint32_t a;
    asm("{ .reg .u64 t; cvta.to.shared.u64 t, %1; cvt.u32.u64 %0, t; }"
        : "=r"(a) : "l"(p));
    return a;
}

__device__ __forceinline__ void ldsm_x4(uint32_t* r, uint32_t addr) {
    asm volatile("ldmatrix.sync.aligned.m8n8.x4.shared.b16 {%0,%1,%2,%3}, [%4];"
                 : "=r"(r[0]), "=r"(r[1]), "=r"(r[2]), "=r"(r[3]) : "r"(addr));
}

__device__ __forceinline__ void mma_bf16(float* c, const uint32_t* a,
                                         const uint32_t* b) {
    asm volatile(
        "mma.sync.aligned.m16n8k16.row.col.f32.bf16.bf16.f32 "
        "{%0,%1,%2,%3}, {%4,%5,%6,%7}, {%8,%9}, {%0,%1,%2,%3};"
        : "+f"(c[0]), "+f"(c[1]), "+f"(c[2]), "+f"(c[3])
        : "r"(a[0]), "r"(a[1]), "r"(a[2]), "r"(a[3]), "r"(b[0]), "r"(b[1]));
}

__device__ __forceinline__ void cpasync16(uint32_t dst, const void* src) {
    asm volatile("cp.async.cg.shared.global [%0], [%1], 16;"
                 :: "r"(dst), "l"(src) : "memory");
}
#define CP_COMMIT() asm volatile("cp.async.commit_group;" ::: "memory")
#define CP_WAIT(n)  asm volatile("cp.async.wait_group %0;" :: "n"(n) : "memory")

// =====================================================================
// fp32 -> bf16 hi/lo split, vectorized (exact residual: lo = bf16(x - hi))
// =====================================================================
__global__ __launch_bounds__(256)
void cvt_hilo_kernel(const float* __restrict__ x,
                     __nv_bfloat16* __restrict__ hi,
                     __nv_bfloat16* __restrict__ lo, int n4)
{
    int i = blockIdx.x * blockDim.x + threadIdx.x;
    if (i >= n4) return;
    float4 v = ((const float4*)x)[i];
    __nv_bfloat16 h0 = __float2bfloat16(v.x);
    __nv_bfloat16 h1 = __float2bfloat16(v.y);
    __nv_bfloat16 h2 = __float2bfloat16(v.z);
    __nv_bfloat16 h3 = __float2bfloat16(v.w);
    __nv_bfloat16 l0 = __float2bfloat16(v.x - __bfloat162float(h0));
    __nv_bfloat16 l1 = __float2bfloat16(v.y - __bfloat162float(h1));
    __nv_bfloat16 l2 = __float2bfloat16(v.z - __bfloat162float(h2));
    __nv_bfloat16 l3 = __float2bfloat16(v.w - __bfloat162float(h3));
    uint2 uh = make_uint2(
        (uint32_t)__bfloat16_as_ushort(h0) | ((uint32_t)__bfloat16_as_ushort(h1) << 16),
        (uint32_t)__bfloat16_as_ushort(h2) | ((uint32_t)__bfloat16_as_ushort(h3) << 16));
    uint2 ul = make_uint2(
        (uint32_t)__bfloat16_as_ushort(l0) | ((uint32_t)__bfloat16_as_ushort(l1) << 16),
        (uint32_t)__bfloat16_as_ushort(l2) | ((uint32_t)__bfloat16_as_ushort(l3) << 16));
    ((uint2*)hi)[i] = uh;
    ((uint2*)lo)[i] = ul;
}

// =====================================================================
// Tensor-core GEMM (mma.sync bf16, 3-pass hi/lo, cp.async 3-stage):
//   C = A (MxK rm) * B^T (B is NxK rm), M=4096 N=1024 K=1024.
// CTA tile 128(M) x 128(N), BK=32. 8 warps = 2(m) x 4(n), warp tile 64x32.
// smem: rows of 64B (32 bf16), 16B-chunk XOR swizzle ch^=(row>>1)&3.
// Stage = Ahi(8K) Alo(8K) Bhi(8K) Blo(8K) = 32KB; 3 stages = 96KB.
// ACC is [4 mf][4 nf][4] = 64 floats (round-8 bug: was sized [2][..]).
// mode 0: C[m*N+n];  mode 1: head-split [(b*H+h)*S+s]*64+hd.
// =====================================================================
#define GSTG 32768
#define GOFF_ALO 8192
#define GOFF_BHI 16384
#define GOFF_BLO 24576
#define GEMM_SMEM (3*GSTG)

__global__ __launch_bounds__(256, 2)
void gemm_mma_kernel(const __nv_bfloat16* __restrict__ Ahi,
                     const __nv_bfloat16* __restrict__ Alo,
                     const __nv_bfloat16* __restrict__ Bhi,
                     const __nv_bfloat16* __restrict__ Blo,
                     float* __restrict__ C, int mode)
{
    extern __shared__ __align__(16) char gsm[];
    const uint32_t sbase = smem_u32(gsm);

    const int tid  = threadIdx.x;
    const int wid  = tid >> 5;
    const int lane = tid & 31;
    const int m0 = blockIdx.y * 128;
    const int n0 = blockIdx.x * 128;
    const int wm0 = (wid & 1) * 64;    // warp m offset (0/64)
    const int wn0 = (wid >> 1) * 32;   // warp n offset (0/32/64/96)

    // ldmatrix lane mapping (identical to validated round-7 kernel)
    const int mt = lane >> 3;
    const int rr = lane & 7;
    const int a_row = rr + 8 * (mt & 1);
    const int a_kof = 8 * (mt >> 1);
    const int b_row = rr + 8 * (mt >> 1);
    const int b_kof = 8 * (mt & 1);

    // per-thread cp.async slots: 2 chunk-slots per buffer
    const int ld_r0 = tid >> 2;            // 0..63
    const int ld_c0 = tid & 3;
    const int ld_r1 = ld_r0 + 64;          // 64..127

    float acc[4][4][4];                    // [mf][nf][4]  -- FIXED SIZE
    #pragma unroll
    for (int i = 0; i < 4; i++)
        #pragma unroll
        for (int j = 0; j < 4; j++)
            #pragma unroll
            for (int e = 0; e < 4; e++) acc[i][j][e] = 0.0f;

    auto issue_stage = [&](int ch, int stg) {
        const int k0 = ch * 32;
        const uint32_t sst = sbase + stg * GSTG;
        {
            const int r = ld_r0, c = ld_c0;
            const uint32_t sw = (uint32_t)(r * 64 + ((c ^ ((r >> 1) & 3)) << 4));
            const size_t goA = (size_t)(m0 + r) * Dq + k0 + c * 8;
            const size_t goB = (size_t)(n0 + r) * Dq + k0 + c * 8;
            cpasync16(sst + sw,            Ahi + goA);
            cpasync16(sst + GOFF_ALO + sw, Alo + goA);
            cpasync16(sst + GOFF_BHI + sw, Bhi + goB);
            cpasync16(sst + GOFF_BLO + sw, Blo + goB);
        }
        {
            const int r = ld_r1, c = ld_c0;
            const uint32_t sw = (uint32_t)(r * 64 + ((c ^ ((r >> 1) & 3)) << 4));
            const size_t goA = (size_t)(m0 + r) * Dq + k0 + c * 8;
            const size_t goB = (size_t)(n0 + r) * Dq + k0 + c * 8;
            cpasync16(sst + sw,            Ahi + goA);
            cpasync16(sst + GOFF_ALO + sw, Alo + goA);
            cpasync16(sst + GOFF_BHI + sw, Bhi + goB);
            cpasync16(sst + GOFF_BLO + sw, Blo + goB);
        }
    };

    // prologue: stages 0,1 in flight
    issue_stage(0, 0); CP_COMMIT();
    issue_stage(1, 1); CP_COMMIT();

    const int NCH = Dq / 32;   // 32
    for (int ch = 0; ch < NCH; ch++) {
        CP_WAIT(1);            // stage ch complete (one younger group may fly)
        __syncthreads();       // all warps done computing stage (ch+2)%3's slot
        if (ch + 2 < NCH) issue_stage(ch + 2, (ch + 2) % 3);
        CP_COMMIT();           // commit every iter keeps group count uniform

        const uint32_t sst = sbase + (ch % 3) * GSTG;
        #pragma unroll
        for (int ks = 0; ks < 32; ks += 16) {
            uint32_t bhi[2][4], blo[2][4];
            #pragma unroll
            for (int p = 0; p < 2; p++) {
                const int row = wn0 + p * 16 + b_row;
                const int cch = (ks + b_kof) >> 3;
                const uint32_t ad = sst + GOFF_BHI +
                    (uint32_t)(row * 64 + ((cch ^ ((row >> 1) & 3)) << 4));
                ldsm_x4(bhi[p], ad);
                ldsm_x4(blo[p], ad + (GOFF_BLO - GOFF_BHI));
            }
            #pragma unroll
            for (int mf = 0; mf < 4; mf++) {
                const int row = wm0 + mf * 16 + a_row;
                const int cch = (ks + a_kof) >> 3;
                const uint32_t ad = sst +
                    (uint32_t)(row * 64 + ((cch ^ ((row >> 1) & 3)) << 4));
                uint32_t ahi[4], alo[4];
                ldsm_x4(ahi, ad);
                ldsm_x4(alo, ad + GOFF_ALO);
                #pragma unroll
                for (int nf = 0; nf < 4; nf++) {
                    const uint32_t* bh = &bhi[nf >> 1][(nf & 1) * 2];
                    const uint32_t* bl = &blo[nf >> 1][(nf & 1) * 2];
                    mma_bf16(acc[mf][nf], ahi, bh);
                    mma_bf16(acc[mf][nf], ahi, bl);
                    mma_bf16(acc[mf][nf], alo, bh);
                }
            }
        }
    }
    __syncthreads();

    // epilogue: m16n8 accum: c0,c1 @(g, cc..cc+1), c2,c3 @(g+8, cc..cc+1)
    const int g  = lane >> 2;
    const int cc = (lane & 3) * 2;
    #pragma unroll
    for (int mf = 0; mf < 4; mf++)
        #pragma unroll
        for (int nf = 0; nf < 4; nf++) {
            const int mA = m0 + wm0 + mf * 16 + g;
            const int nA = n0 + wn0 + nf * 8 + cc;
            #pragma unroll
            for (int half = 0; half < 2; half++) {
                const int m = mA + half * 8;
                float2 v = make_float2(acc[mf][nf][half * 2],
                                       acc[mf][nf][half * 2 + 1]);
                if (mode == 0) {
                    *(float2*)(C + (size_t)m * Dq + nA) = v;
                } else {
                    const int bb = m >> 11;
                    const int ss = m & (Sq - 1);
                    const int hh = nA >> 6;
                    const int hd = nA & 63;
                    *(float2*)(C + (((size_t)(bb * Hq + hh) * Sq + ss) * HDq + hd)) = v;
                }
            }
        }
}

// =====================================================================
// Flash attention (unchanged from round 7 — passing): per block = one
// (b,h) and one 128-row Q chunk. 128 threads (16 ty x 8 tx), 8x8
// microtile. Exact reference masking semantics.
// =====================================================================
#define QST 132
#define KST 68

__global__ __launch_bounds__(128)
void attn_kernel(const float* __restrict__ qh,
                 const float* __restrict__ kh,
                 const float* __restrict__ vh,
                 const int*   __restrict__ attn_mask,
                 const int*   __restrict__ mask_future_p,
                 float* __restrict__ ctx)
{
    extern __shared__ float sm[];
    float* Qs = sm;                    // [d=64][q=128] stride QST
    float* Ks = Qs + 64 * QST;         // [d=64][kv=64] stride KST
    float* Vs = Ks + 64 * KST;         // [kv=64][d=64] stride KST
    float* Ps = Vs + 64 * KST;         // [q=128][kv=64] stride KST
    __shared__ int   padm[64];
    __shared__ float wred[4];
    __shared__ int   s_needtail;

    const int bh = blockIdx.y;
    const int b  = bh / Hq;
    const int h  = bh % Hq;
    const int qb = blockIdx.x;
    const int qr0 = qb * 128;
    const int tid = threadIdx.x;
    const int tx = tid & 7;
    const int ty = tid >> 3;
    const int mask_future = mask_future_p[0];

    {
        const float* Qg = qh + ((size_t)bh * Sq + qr0) * HDq;
        for (int e = tid; e < 128 * 16; e += 128) {
            const int r = e >> 4, c = e & 15;
            float4 v = *(const float4*)(Qg + (size_t)r * HDq + c * 4);
            float* p = Qs + (c * 4) * QST + r;
            p[0]       = v.x * 0.125f;
            p[QST]     = v.y * 0.125f;
            p[2 * QST] = v.z * 0.125f;
            p[3 * QST] = v.w * 0.125f;
        }
    }

    float m_[8], l_[8], o_[8][8];
    #pragma unroll
    for (int i = 0; i < 8; i++) {
        m_[i] = -1e30f; l_[i] = 0.0f;
        #pragma unroll
        for (int j = 0; j < 8; j++) o_[i][j] = 0.0f;
    }

    const int ntiles = Sq / 64;
    const int limit = mask_future ? (2 * qb + 2) : ntiles;

    for (int phase = 0; phase < 2; phase++) {
        int t0, t1;
        if (phase == 0) { t0 = 0; t1 = limit; }
        else {
            if (!mask_future || limit >= ntiles) break;
            float mymin = m_[0];
            #pragma unroll
            for (int i = 1; i < 8; i++) mymin = fminf(mymin, m_[i]);
            #pragma unroll
            for (int off = 16; off > 0; off >>= 1)
                mymin = fminf(mymin, __shfl_xor_sync(0xffffffffu, mymin, off));
            __syncthreads();
            if ((tid & 31) == 0) wred[tid >> 5] = mymin;
            __syncthreads();
            if (tid == 0) {
                float mn = fminf(fminf(wred[0], wred[1]), fminf(wred[2], wred[3]));
                s_needtail = (mn < -5000.0f) ? 1 : 0;
            }
            __syncthreads();
            if (!s_needtail) break;
            t0 = limit; t1 = ntiles;
        }

        for (int t = t0; t < t1; t++) {
            const int kv0 = t * 64;
            const float* Kg = kh + ((size_t)bh * Sq + kv0) * HDq;
            const float* Vg = vh + ((size_t)bh * Sq + kv0) * HDq;
            __syncthreads();
            for (int e = tid; e < 64 * 16; e += 128) {
                const int r = e >> 4, c = e & 15;
                float4 kv4 = *(const float4*)(Kg + (size_t)r * HDq + c * 4);
                float* p = Ks + (c * 4) * KST + r;
                p[0]       = kv4.x;
                p[KST]     = kv4.y;
                p[2 * KST] = kv4.z;
                p[3 * KST] = kv4.w;
                *(float4*)(Vs + r * KST + c * 4) =
                    *(const float4*)(Vg + (size_t)r * HDq + c * 4);
            }
            if (tid < 64) padm[tid] = attn_mask[(size_t)b * Sq + kv0 + tid];
            __syncthreads();

            float cacc[8][8];
            #pragma unroll
            for (int i = 0; i < 8; i++)
                #pragma unroll
                for (int j = 0; j < 8; j++) cacc[i][j] = 0.0f;
            for (int d = 0; d < 64; d++) {
                float4 a0 = *(const float4*)(Qs + d * QST + ty * 8);
                float4 a1 = *(const float4*)(Qs + d * QST + ty * 8 + 4);
                float4 b0 = *(const float4*)(Ks + d * KST + tx * 8);
                float4 b1 = *(const float4*)(Ks + d * KST + tx * 8 + 4);
                float av[8] = {a0.x, a0.y, a0.z, a0.w, a1.x, a1.y, a1.z, a1.w};
                float bv[8] = {b0.x, b0.y, b0.z, b0.w, b1.x, b1.y, b1.z, b1.w};
                #pragma unroll
                for (int i = 0; i < 8; i++)
                    #pragma unroll
                    for (int j = 0; j < 8; j++) cacc[i][j] += av[i] * bv[j];
            }

            #pragma unroll
            for (int i = 0; i < 8; i++) {
                const int grow = qr0 + ty * 8 + i;
                #pragma unroll
                for (int j = 0; j < 8; j++) {
                    const int lcol = tx * 8 + j;
                    const int gcol = kv0 + lcol;
                    float sv = cacc[i][j];
                    if (mask_future && (gcol > grow)) sv += NEGV;
                    if (padm[lcol] == 0) sv = NEGV;
                    cacc[i][j] = sv;
                }
            }

            #pragma unroll
            for (int i = 0; i < 8; i++) {
                float tmax = cacc[i][0];
                #pragma unroll
                for (int j = 1; j < 8; j++) tmax = fmaxf(tmax, cacc[i][j]);
                #pragma unroll
                for (int off = 4; off > 0; off >>= 1)
                    tmax = fmaxf(tmax, __shfl_xor_sync(0xffffffffu, tmax, off));
                const float mnew  = fmaxf(m_[i], tmax);
                const float alpha = __expf(m_[i] - mnew);
                float rs = 0.0f;
                #pragma unroll
                for (int j = 0; j < 8; j++) {
                    const float p = __expf(cacc[i][j] - mnew);
                    cacc[i][j] = p;
                    rs += p;
                }
                #pragma unroll
                for (int off = 4; off > 0; off >>= 1)
                    rs += __shfl_xor_sync(0xffffffffu, rs, off);
                l_[i] = l_[i] * alpha + rs;
                m_[i] = mnew;
                #pragma unroll
                for (int j = 0; j < 8; j++) o_[i][j] *= alpha;
                *(float4*)(Ps + (ty * 8 + i) * KST + tx * 8) =
                    make_float4(cacc[i][0], cacc[i][1], cacc[i][2], cacc[i][3]);
                *(float4*)(Ps + (ty * 8 + i) * KST + tx * 8 + 4) =
                    make_float4(cacc[i][4], cacc[i][5], cacc[i][6], cacc[i][7]);
            }
            __syncthreads();

            for (int kv = 0; kv < 64; kv += 4) {
                float4 p4[8];
                #pragma unroll
                for (int i = 0; i < 8; i++)
                    p4[i] = *(const float4*)(Ps + (ty * 8 + i) * KST + kv);
                float4 va[4], vb[4];
                #pragma unroll
                for (int tt = 0; tt < 4; tt++) {
                    va[tt] = *(const float4*)(Vs + (kv + tt) * KST + tx * 8);
                    vb[tt] = *(const float4*)(Vs + (kv + tt) * KST + tx * 8 + 4);
                }
                #pragma unroll
                for (int i = 0; i < 8; i++) {
                    const float pv[4] = {p4[i].x, p4[i].y, p4[i].z, p4[i].w};
                    #pragma unroll
                    for (int tt = 0; tt < 4; tt++) {
                        o_[i][0] += pv[tt] * va[tt].x;
                        o_[i][1] += pv[tt] * va[tt].y;
                        o_[i][2] += pv[tt] * va[tt].z;
                        o_[i][3] += pv[tt] * va[tt].w;
                        o_[i][4] += pv[tt] * vb[tt].x;
                        o_[i][5] += pv[tt] * vb[tt].y;
                        o_[i][6] += pv[tt] * vb[tt].z;
                        o_[i][7] += pv[tt] * vb[tt].w;
                    }
                }
            }
        }
    }

    #pragma unroll
    for (int i = 0; i < 8; i++) {
        const float inv = 1.0f / l_[i];
        const int grow = qr0 + ty * 8 + i;
        float* dst = ctx + ((size_t)b * Sq + grow) * Dq + h * HDq + tx * 8;
        *(float4*)(dst) = make_float4(o_[i][0] * inv, o_[i][1] * inv,
                                      o_[i][2] * inv, o_[i][3] * inv);
        *(float4*)(dst + 4) = make_float4(o_[i][4] * inv, o_[i][5] * inv,
                                          o_[i][6] * inv, o_[i][7] * inv);
    }
}

// =====================================================================
// launch
// =====================================================================
extern "C" void kernel_launch(void* const* d_in, const int* in_sizes, int n_in,
                              void* d_out, int out_size)
{
    const float* q   = (const float*)d_in[0];
    const float* k   = (const float*)d_in[1];
    const float* v   = (const float*)d_in[2];
    const int*   am  = (const int*)  d_in[3];
    const float* Wq  = (const float*)d_in[4];
    const float* Wk  = (const float*)d_in[5];
    const float* Wv  = (const float*)d_in[6];
    const float* Wo  = (const float*)d_in[7];
    const int*   mf  = (const int*)  d_in[8];
    float* out = (float*)d_out;

    float *qh, *kh, *vh, *ctx;
    cudaGetSymbolAddress((void**)&qh,  g_qh);
    cudaGetSymbolAddress((void**)&kh,  g_kh);
    cudaGetSymbolAddress((void**)&vh,  g_vh);
    cudaGetSymbolAddress((void**)&ctx, g_ctx);

    __nv_bfloat16 *qhi, *qlo, *khi, *klo, *vhi, *vlo, *chi, *clo;
    __nv_bfloat16 *wqhi, *wqlo, *wkhi, *wklo, *wvhi, *wvlo, *wohi, *wolo;
    cudaGetSymbolAddress((void**)&qhi,  g_q_hi);  cudaGetSymbolAddress((void**)&qlo,  g_q_lo);
    cudaGetSymbolAddress((void**)&khi,  g_k_hi);  cudaGetSymbolAddress((void**)&klo,  g_k_lo);
    cudaGetSymbolAddress((void**)&vhi,  g_v_hi);  cudaGetSymbolAddress((void**)&vlo,  g_v_lo);
    cudaGetSymbolAddress((void**)&chi,  g_c_hi);  cudaGetSymbolAddress((void**)&clo,  g_c_lo);
    cudaGetSymbolAddress((void**)&wqhi, g_wq_hi); cudaGetSymbolAddress((void**)&wqlo, g_wq_lo);
    cudaGetSymbolAddress((void**)&wkhi, g_wk_hi); cudaGetSymbolAddress((void**)&wklo, g_wk_lo);
    cudaGetSymbolAddress((void**)&wvhi, g_wv_hi); cudaGetSymbolAddress((void**)&wvlo, g_wv_lo);
    cudaGetSymbolAddress((void**)&wohi, g_wo_hi); cudaGetSymbolAddress((void**)&wolo, g_wo_lo);

    const int attn_smem =
        (64 * QST + 64 * KST + 64 * KST + 128 * KST) * (int)sizeof(float);
    cudaFuncSetAttribute(attn_kernel,
                         cudaFuncAttributeMaxDynamicSharedMemorySize, attn_smem);
    cudaFuncSetAttribute(gemm_mma_kernel,
                         cudaFuncAttributeMaxDynamicSharedMemorySize, GEMM_SMEM);

    // --- hi/lo conversions ---
    const int nIn4 = Mq * Dq / 4;
    const int nW4  = Dq * Dq / 4;
    cvt_hilo_kernel<<<nIn4 / 256, 256>>>(q,  qhi,  qlo,  nIn4);
    cvt_hilo_kernel<<<nIn4 / 256, 256>>>(k,  khi,  klo,  nIn4);
    cvt_hilo_kernel<<<nIn4 / 256, 256>>>(v,  vhi,  vlo,  nIn4);
    cvt_hilo_kernel<<<nW4 / 256,  256>>>(Wq, wqhi, wqlo, nW4);
    cvt_hilo_kernel<<<nW4 / 256,  256>>>(Wk, wkhi, wklo, nW4);
    cvt_hilo_kernel<<<nW4 / 256,  256>>>(Wv, wvhi, wvlo, nW4);
    cvt_hilo_kernel<<<nW4 / 256,  256>>>(Wo, wohi, wolo, nW4);

    // --- projections (tensor cores, pipelined) ---
    dim3 gemm_grid(Dq / 128, Mq / 128);   // (8, 32) = 256 CTAs
    gemm_mma_kernel<<<gemm_grid, 256, GEMM_SMEM>>>(qhi, qlo, wqhi, wqlo, qh, 1);
    gemm_mma_kernel<<<gemm_grid, 256, GEMM_SMEM>>>(khi, klo, wkhi, wklo, kh, 1);
    gemm_mma_kernel<<<gemm_grid, 256, GEMM_SMEM>>>(vhi, vlo, wvhi, wvlo, vh, 1);

    // --- attention ---
    dim3 attn_grid(Sq / 128, Bq * Hq);
    attn_kernel<<<attn_grid, 128, attn_smem>>>(qh, kh, vh, am, mf, ctx);

    // --- output projection ---
    cvt_hilo_kernel<<<nIn4 / 256, 256>>>(ctx, chi, clo, nIn4);
    gemm_mma_kernel<<<gemm_grid, 256, GEMM_SMEM>>>(chi, clo, wohi, wolo, out, 0);
}

// round 10
// speedup vs baseline: 1.8745x; 1.0105x over previous
#include <cuda_runtime.h>
#include <cuda_bf16.h>
#include <math.h>
#include <stdint.h>

// ---------------- problem constants ----------------
#define Bq   2
#define Sq   2048
#define Dq   1024
#define Hq   16
#define HDq  64
#define Mq   (Bq*Sq)          // 4096
#define NEGV (-10000.0f)

// ---------------- scratch (device globals; no allocation allowed) ----------
__device__ float g_qh[Bq*Hq*Sq*HDq];   // [b][h][s][hd]
__device__ float g_kh[Bq*Hq*Sq*HDq];
__device__ float g_vh[Bq*Hq*Sq*HDq];
__device__ float g_ctx[Bq*Sq*Dq];      // merged [b*S+s][h*64+hd]

// bf16 hi/lo copies for tensor-core GEMMs
__device__ __nv_bfloat16 g_q_hi[Mq*Dq],  g_q_lo[Mq*Dq];
__device__ __nv_bfloat16 g_k_hi[Mq*Dq],  g_k_lo[Mq*Dq];
__device__ __nv_bfloat16 g_v_hi[Mq*Dq],  g_v_lo[Mq*Dq];
__device__ __nv_bfloat16 g_c_hi[Mq*Dq],  g_c_lo[Mq*Dq];
__device__ __nv_bfloat16 g_wq_hi[Dq*Dq], g_wq_lo[Dq*Dq];
__device__ __nv_bfloat16 g_wk_hi[Dq*Dq], g_wk_lo[Dq*Dq];
__device__ __nv_bfloat16 g_wv_hi[Dq*Dq], g_wv_lo[Dq*Dq];
__device__ __nv_bfloat16 g_wo_hi[Dq*Dq], g_wo_lo[Dq*Dq];

// =====================================================================
// helpers
// =====================================================================
__device__ __forceinline__ uint32_t smem_u32(const void* p) {
    uint32_t a;
    asm("{ .reg .u64 t; cvta.to.shared.u64 t, %1; cvt.u32.u64 %0, t; }"
        : "=r"(a) : "l"(p));
    return a;
}

__device__ __forceinline__ void ldsm_x4(uint32_t* r, uint32_t addr) {
    asm volatile("ldmatrix.sync.aligned.m8n8.x4.shared.b16 {%0,%1,%2,%3}, [%4];"
                 : "=r"(r[0]), "=r"(r[1]), "=r"(r[2]), "=r"(r[3]) : "r"(addr));
}

__device__ __forceinline__ void mma_bf16(float* c, const uint32_t* a,
                                         const uint32_t* b) {
    asm volatile(
        "mma.sync.aligned.m16n8k16.row.col.f32.bf16.bf16.f32 "
        "{%0,%1,%2,%3}, {%4,%5,%6,%7}, {%8,%9}, {%0,%1,%2,%3};"
        : "+f"(c[0]), "+f"(c[1]), "+f"(c[2]), "+f"(c[3])
        : "r"(a[0]), "r"(a[1]), "r"(a[2]), "r"(a[3]), "r"(b[0]), "r"(b[1]));
}

__device__ __forceinline__ void cpasync16(uint32_t dst, const void* src) {
    asm volatile("cp.async.cg.shared.global [%0], [%1], 16;"
                 :: "r"(dst), "l"(src) : "memory");
}
#define CP_COMMIT() asm volatile("cp.async.commit_group;" ::: "memory")
#define CP_WAIT(n)  asm volatile("cp.async.wait_group %0;" :: "n"(n) : "memory")

// Fast exp for x <= 0 on the FMA/ALU pipes only (no MUFU, no F2I).
// exp(x) = 2^(x*log2e); round via the 2^23+2^22 magic number, rebuild the
// power-of-two with integer ops, degree-5 Taylor for 2^f on [-0.5, 0.5]
// (max rel err ~2.4e-6). Clamped at -80 (exp(-80)=1.8e-35, negligible).
__device__ __forceinline__ float fexp_neg(float x) {
    x = fmaxf(x, -80.0f);
    const float y = x * 1.4426950408889634f;
    const float t = y + 12582912.0f;          // round-to-nearest int
    const float nf = t - 12582912.0f;
    const float f = y - nf;                   // exact (Sterbenz)
    const uint32_t sb = (__float_as_uint(t) + (127u - 0x400000u)) << 23;
    float p = 0.0013333558f;
    p = fmaf(p, f, 0.0096181291f);
    p = fmaf(p, f, 0.0555041087f);
    p = fmaf(p, f, 0.2402265069f);
    p = fmaf(p, f, 0.6931471806f);
    p = fmaf(p, f, 1.0f);
    return p * __uint_as_float(sb);
}

// =====================================================================
// fp32 -> bf16 hi/lo split (exact residual: lo = bf16(x - hi))
// =====================================================================
__device__ __forceinline__ void cvt_body(const float* __restrict__ x,
                                         __nv_bfloat16* __restrict__ hi,
                                         __nv_bfloat16* __restrict__ lo,
                                         int n4)
{
    int i = blockIdx.x * blockDim.x + threadIdx.x;
    if (i >= n4) return;
    float4 v = ((const float4*)x)[i];
    __nv_bfloat16 h0 = __float2bfloat16(v.x);
    __nv_bfloat16 h1 = __float2bfloat16(v.y);
    __nv_bfloat16 h2 = __float2bfloat16(v.z);
    __nv_bfloat16 h3 = __float2bfloat16(v.w);
    __nv_bfloat16 l0 = __float2bfloat16(v.x - __bfloat162float(h0));
    __nv_bfloat16 l1 = __float2bfloat16(v.y - __bfloat162float(h1));
    __nv_bfloat16 l2 = __float2bfloat16(v.z - __bfloat162float(h2));
    __nv_bfloat16 l3 = __float2bfloat16(v.w - __bfloat162float(h3));
    uint2 uh = make_uint2(
        (uint32_t)__bfloat16_as_ushort(h0) | ((uint32_t)__bfloat16_as_ushort(h1) << 16),
        (uint32_t)__bfloat16_as_ushort(h2) | ((uint32_t)__bfloat16_as_ushort(h3) << 16));
    uint2 ul = make_uint2(
        (uint32_t)__bfloat16_as_ushort(l0) | ((uint32_t)__bfloat16_as_ushort(l1) << 16),
        (uint32_t)__bfloat16_as_ushort(l2) | ((uint32_t)__bfloat16_as_ushort(l3) << 16));
    ((uint2*)hi)[i] = uh;
    ((uint2*)lo)[i] = ul;
}

__global__ __launch_bounds__(256)
void cvt_hilo_kernel(const float* __restrict__ x,
                     __nv_bfloat16* __restrict__ hi,
                     __nv_bfloat16* __restrict__ lo, int n4)
{ cvt_body(x, hi, lo, n4); }

// fused z=3 (q,k,v inputs)
__global__ __launch_bounds__(256)
void cvt_hilo3_kernel(const float* x0, const float* x1, const float* x2,
                      __nv_bfloat16* h0, __nv_bfloat16* l0,
                      __nv_bfloat16* h1, __nv_bfloat16* l1,
                      __nv_bfloat16* h2, __nv_bfloat16* l2, int n4)
{
    const float* x; __nv_bfloat16 *hh, *ll;
    switch (blockIdx.z) {
        case 0:  x = x0; hh = h0; ll = l0; break;
        case 1:  x = x1; hh = h1; ll = l1; break;
        default: x = x2; hh = h2; ll = l2; break;
    }
    cvt_body(x, hh, ll, n4);
}

// fused z=4 (weights)
__global__ __launch_bounds__(256)
void cvt_hilo4_kernel(const float* x0, const float* x1, const float* x2, const float* x3,
                      __nv_bfloat16* h0, __nv_bfloat16* l0,
                      __nv_bfloat16* h1, __nv_bfloat16* l1,
                      __nv_bfloat16* h2, __nv_bfloat16* l2,
                      __nv_bfloat16* h3, __nv_bfloat16* l3, int n4)
{
    const float* x; __nv_bfloat16 *hh, *ll;
    switch (blockIdx.z) {
        case 0:  x = x0; hh = h0; ll = l0; break;
        case 1:  x = x1; hh = h1; ll = l1; break;
        case 2:  x = x2; hh = h2; ll = l2; break;
        default: x = x3; hh = h3; ll = l3; break;
    }
    cvt_body(x, hh, ll, n4);
}

// =====================================================================
// Tensor-core GEMM body (identical math to passing round-9 kernel):
//   C = A (MxK rm) * B^T (B is NxK rm), M=4096 N=1024 K=1024.
// CTA tile 128x128, BK=32, 8 warps = 2(m) x 4(n), warp tile 64x32.
// cp.async 3-stage, 16B-chunk XOR swizzle ch^=(row>>1)&3.
// =====================================================================
#define GSTG 32768
#define GOFF_ALO 8192
#define GOFF_BHI 16384
#define GOFF_BLO 24576
#define GEMM_SMEM (3*GSTG)

__device__ __forceinline__
void gemm_body(char* gsm,
               const __nv_bfloat16* __restrict__ Ahi,
               const __nv_bfloat16* __restrict__ Alo,
               const __nv_bfloat16* __restrict__ Bhi,
               const __nv_bfloat16* __restrict__ Blo,
               float* __restrict__ C, int mode)
{
    const uint32_t sbase = smem_u32(gsm);

    const int tid  = threadIdx.x;
    const int wid  = tid >> 5;
    const int lane = tid & 31;
    const int m0 = blockIdx.y * 128;
    const int n0 = blockIdx.x * 128;
    const int wm0 = (wid & 1) * 64;
    const int wn0 = (wid >> 1) * 32;

    const int mt = lane >> 3;
    const int rr = lane & 7;
    const int a_row = rr + 8 * (mt & 1);
    const int a_kof = 8 * (mt >> 1);
    const int b_row = rr + 8 * (mt >> 1);
    const int b_kof = 8 * (mt & 1);

    const int ld_r0 = tid >> 2;
    const int ld_c0 = tid & 3;
    const int ld_r1 = ld_r0 + 64;

    float acc[4][4][4];
    #pragma unroll
    for (int i = 0; i < 4; i++)
        #pragma unroll
        for (int j = 0; j < 4; j++)
            #pragma unroll
            for (int e = 0; e < 4; e++) acc[i][j][e] = 0.0f;

    auto issue_stage = [&](int ch, int stg) {
        const int k0 = ch * 32;
        const uint32_t sst = sbase + stg * GSTG;
        {
            const int r = ld_r0, c = ld_c0;
            const uint32_t sw = (uint32_t)(r * 64 + ((c ^ ((r >> 1) & 3)) << 4));
            const size_t goA = (size_t)(m0 + r) * Dq + k0 + c * 8;
            const size_t goB = (size_t)(n0 + r) * Dq + k0 + c * 8;
            cpasync16(sst + sw,            Ahi + goA);
            cpasync16(sst + GOFF_ALO + sw, Alo + goA);
            cpasync16(sst + GOFF_BHI + sw, Bhi + goB);
            cpasync16(sst + GOFF_BLO + sw, Blo + goB);
        }
        {
            const int r = ld_r1, c = ld_c0;
            const uint32_t sw = (uint32_t)(r * 64 + ((c ^ ((r >> 1) & 3)) << 4));
            const size_t goA = (size_t)(m0 + r) * Dq + k0 + c * 8;
            const size_t goB = (size_t)(n0 + r) * Dq + k0 + c * 8;
            cpasync16(sst + sw,            Ahi + goA);
            cpasync16(sst + GOFF_ALO + sw, Alo + goA);
            cpasync16(sst + GOFF_BHI + sw, Bhi + goB);
            cpasync16(sst + GOFF_BLO + sw, Blo + goB);
        }
    };

    issue_stage(0, 0); CP_COMMIT();
    issue_stage(1, 1); CP_COMMIT();

    const int NCH = Dq / 32;   // 32
    for (int ch = 0; ch < NCH; ch++) {
        CP_WAIT(1);
        __syncthreads();
        if (ch + 2 < NCH) issue_stage(ch + 2, (ch + 2) % 3);
        CP_COMMIT();

        const uint32_t sst = sbase + (ch % 3) * GSTG;
        #pragma unroll
        for (int ks = 0; ks < 32; ks += 16) {
            uint32_t bhi[2][4], blo[2][4];
            #pragma unroll
            for (int p = 0; p < 2; p++) {
                const int row = wn0 + p * 16 + b_row;
                const int cch = (ks + b_kof) >> 3;
                const uint32_t ad = sst + GOFF_BHI +
                    (uint32_t)(row * 64 + ((cch ^ ((row >> 1) & 3)) << 4));
                ldsm_x4(bhi[p], ad);
                ldsm_x4(blo[p], ad + (GOFF_BLO - GOFF_BHI));
            }
            #pragma unroll
            for (int mf = 0; mf < 4; mf++) {
                const int row = wm0 + mf * 16 + a_row;
                const int cch = (ks + a_kof) >> 3;
                const uint32_t ad = sst +
                    (uint32_t)(row * 64 + ((cch ^ ((row >> 1) & 3)) << 4));
                uint32_t ahi[4], alo[4];
                ldsm_x4(ahi, ad);
                ldsm_x4(alo, ad + GOFF_ALO);
                #pragma unroll
                for (int nf = 0; nf < 4; nf++) {
                    const uint32_t* bh = &bhi[nf >> 1][(nf & 1) * 2];
                    const uint32_t* bl = &blo[nf >> 1][(nf & 1) * 2];
                    mma_bf16(acc[mf][nf], ahi, bh);
                    mma_bf16(acc[mf][nf], ahi, bl);
                    mma_bf16(acc[mf][nf], alo, bh);
                }
            }
        }
    }
    __syncthreads();

    const int g  = lane >> 2;
    const int cc = (lane & 3) * 2;
    #pragma unroll
    for (int mf = 0; mf < 4; mf++)
        #pragma unroll
        for (int nf = 0; nf < 4; nf++) {
            const int mA = m0 + wm0 + mf * 16 + g;
            const int nA = n0 + wn0 + nf * 8 + cc;
            #pragma unroll
            for (int half = 0; half < 2; half++) {
                const int m = mA + half * 8;
                float2 v = make_float2(acc[mf][nf][half * 2],
                                       acc[mf][nf][half * 2 + 1]);
                if (mode == 0) {
                    *(float2*)(C + (size_t)m * Dq + nA) = v;
                } else {
                    const int bb = m >> 11;
                    const int ss = m & (Sq - 1);
                    const int hh = nA >> 6;
                    const int hd = nA & 63;
                    *(float2*)(C + (((size_t)(bb * Hq + hh) * Sq + ss) * HDq + hd)) = v;
                }
            }
        }
}

// single-output wrapper (Wo projection, mode 0)
__global__ __launch_bounds__(256, 2)
void gemm_mma_kernel(const __nv_bfloat16* __restrict__ Ahi,
                     const __nv_bfloat16* __restrict__ Alo,
                     const __nv_bfloat16* __restrict__ Bhi,
                     const __nv_bfloat16* __restrict__ Blo,
                     float* __restrict__ C, int mode)
{
    extern __shared__ __align__(16) char gsm[];
    gemm_body(gsm, Ahi, Alo, Bhi, Blo, C, mode);
}

// fused QKV wrapper: blockIdx.z selects operand set, mode 1 (head-split)
__global__ __launch_bounds__(256, 2)
void gemm_qkv_kernel(const __nv_bfloat16* qhi, const __nv_bfloat16* qlo,
                     const __nv_bfloat16* khi, const __nv_bfloat16* klo,
                     const __nv_bfloat16* vhi, const __nv_bfloat16* vlo,
                     const __nv_bfloat16* wqhi, const __nv_bfloat16* wqlo,
                     const __nv_bfloat16* wkhi, const __nv_bfloat16* wklo,
                     const __nv_bfloat16* wvhi, const __nv_bfloat16* wvlo,
                     float* qh, float* kh, float* vh)
{
    extern __shared__ __align__(16) char gsm[];
    const __nv_bfloat16 *Ah, *Al, *Bh, *Bl; float* Cp;
    switch (blockIdx.z) {
        case 0:  Ah = qhi; Al = qlo; Bh = wqhi; Bl = wqlo; Cp = qh; break;
        case 1:  Ah = khi; Al = klo; Bh = wkhi; Bl = wklo; Cp = kh; break;
        default: Ah = vhi; Al = vlo; Bh = wvhi; Bl = wvlo; Cp = vh; break;
    }
    gemm_body(gsm, Ah, Al, Bh, Bl, Cp, 1);
}

// =====================================================================
// Flash attention (round-7/9 structure; __expf -> fexp_neg on FMA pipe).
// per block = one (b,h) and one 128-row Q chunk. 128 threads (16x8),
// 8x8 microtile. Exact reference masking semantics.
// =====================================================================
#define QST 132
#define KST 68

__global__ __launch_bounds__(128)
void attn_kernel(const float* __restrict__ qh,
                 const float* __restrict__ kh,
                 const float* __restrict__ vh,
                 const int*   __restrict__ attn_mask,
                 const int*   __restrict__ mask_future_p,
                 float* __restrict__ ctx)
{
    extern __shared__ float sm[];
    float* Qs = sm;                    // [d=64][q=128] stride QST
    float* Ks = Qs + 64 * QST;         // [d=64][kv=64] stride KST
    float* Vs = Ks + 64 * KST;         // [kv=64][d=64] stride KST
    float* Ps = Vs + 64 * KST;         // [q=128][kv=64] stride KST
    __shared__ int   padm[64];
    __shared__ float wred[4];
    __shared__ int   s_needtail;

    const int bh = blockIdx.y;
    const int b  = bh / Hq;
    const int h  = bh % Hq;
    const int qb = blockIdx.x;
    const int qr0 = qb * 128;
    const int tid = threadIdx.x;
    const int tx = tid & 7;
    const int ty = tid >> 3;
    const int mask_future = mask_future_p[0];

    {
        const float* Qg = qh + ((size_t)bh * Sq + qr0) * HDq;
        for (int e = tid; e < 128 * 16; e += 128) {
            const int r = e >> 4, c = e & 15;
            float4 v = *(const float4*)(Qg + (size_t)r * HDq + c * 4);
            float* p = Qs + (c * 4) * QST + r;
            p[0]       = v.x * 0.125f;
            p[QST]     = v.y * 0.125f;
            p[2 * QST] = v.z * 0.125f;
            p[3 * QST] = v.w * 0.125f;
        }
    }

    float m_[8], l_[8], o_[8][8];
    #pragma unroll
    for (int i = 0; i < 8; i++) {
        m_[i] = -1e30f; l_[i] = 0.0f;
        #pragma unroll
        for (int j = 0; j < 8; j++) o_[i][j] = 0.0f;
    }

    const int ntiles = Sq / 64;
    const int limit = mask_future ? (2 * qb + 2) : ntiles;

    for (int phase = 0; phase < 2; phase++) {
        int t0, t1;
        if (phase == 0) { t0 = 0; t1 = limit; }
        else {
            if (!mask_future || limit >= ntiles) break;
            float mymin = m_[0];
            #pragma unroll
            for (int i = 1; i < 8; i++) mymin = fminf(mymin, m_[i]);
            #pragma unroll
            for (int off = 16; off > 0; off >>= 1)
                mymin = fminf(mymin, __shfl_xor_sync(0xffffffffu, mymin, off));
            __syncthreads();
            if ((tid & 31) == 0) wred[tid >> 5] = mymin;
            __syncthreads();
            if (tid == 0) {
                float mn = fminf(fminf(wred[0], wred[1]), fminf(wred[2], wred[3]));
                s_needtail = (mn < -5000.0f) ? 1 : 0;
            }
            __syncthreads();
            if (!s_needtail) break;
            t0 = limit; t1 = ntiles;
        }

        for (int t = t0; t < t1; t++) {
            const int kv0 = t * 64;
            const float* Kg = kh + ((size_t)bh * Sq + kv0) * HDq;
            const float* Vg = vh + ((size_t)bh * Sq + kv0) * HDq;
            __syncthreads();
            for (int e = tid; e < 64 * 16; e += 128) {
                const int r = e >> 4, c = e & 15;
                float4 kv4 = *(const float4*)(Kg + (size_t)r * HDq + c * 4);
                float* p = Ks + (c * 4) * KST + r;
                p[0]       = kv4.x;
                p[KST]     = kv4.y;
                p[2 * KST] = kv4.z;
                p[3 * KST] = kv4.w;
                *(float4*)(Vs + r * KST + c * 4) =
                    *(const float4*)(Vg + (size_t)r * HDq + c * 4);
            }
            if (tid < 64) padm[tid] = attn_mask[(size_t)b * Sq + kv0 + tid];
            __syncthreads();

            float cacc[8][8];
            #pragma unroll
            for (int i = 0; i < 8; i++)
                #pragma unroll
                for (int j = 0; j < 8; j++) cacc[i][j] = 0.0f;
            for (int d = 0; d < 64; d++) {
                float4 a0 = *(const float4*)(Qs + d * QST + ty * 8);
                float4 a1 = *(const float4*)(Qs + d * QST + ty * 8 + 4);
                float4 b0 = *(const float4*)(Ks + d * KST + tx * 8);
                float4 b1 = *(const float4*)(Ks + d * KST + tx * 8 + 4);
                float av[8] = {a0.x, a0.y, a0.z, a0.w, a1.x, a1.y, a1.z, a1.w};
                float bv[8] = {b0.x, b0.y, b0.z, b0.w, b1.x, b1.y, b1.z, b1.w};
                #pragma unroll
                for (int i = 0; i < 8; i++)
                    #pragma unroll
                    for (int j = 0; j < 8; j++) cacc[i][j] += av[i] * bv[j];
            }

            #pragma unroll
            for (int i = 0; i < 8; i++) {
                const int grow = qr0 + ty * 8 + i;
                #pragma unroll
                for (int j = 0; j < 8; j++) {
                    const int lcol = tx * 8 + j;
                    const int gcol = kv0 + lcol;
                    float sv = cacc[i][j];
                    if (mask_future && (gcol > grow)) sv += NEGV;
                    if (padm[lcol] == 0) sv = NEGV;
                    cacc[i][j] = sv;
                }
            }

            #pragma unroll
            for (int i = 0; i < 8; i++) {
                float tmax = cacc[i][0];
                #pragma unroll
                for (int j = 1; j < 8; j++) tmax = fmaxf(tmax, cacc[i][j]);
                #pragma unroll
                for (int off = 4; off > 0; off >>= 1)
                    tmax = fmaxf(tmax, __shfl_xor_sync(0xffffffffu, tmax, off));
                const float mnew  = fmaxf(m_[i], tmax);
                const float alpha = fexp_neg(m_[i] - mnew);
                float rs = 0.0f;
                #pragma unroll
                for (int j = 0; j < 8; j++) {
                    const float p = fexp_neg(cacc[i][j] - mnew);
                    cacc[i][j] = p;
                    rs += p;
                }
                #pragma unroll
                for (int off = 4; off > 0; off >>= 1)
                    rs += __shfl_xor_sync(0xffffffffu, rs, off);
                l_[i] = l_[i] * alpha + rs;
                m_[i] = mnew;
                #pragma unroll
                for (int j = 0; j < 8; j++) o_[i][j] *= alpha;
                *(float4*)(Ps + (ty * 8 + i) * KST + tx * 8) =
                    make_float4(cacc[i][0], cacc[i][1], cacc[i][2], cacc[i][3]);
                *(float4*)(Ps + (ty * 8 + i) * KST + tx * 8 + 4) =
                    make_float4(cacc[i][4], cacc[i][5], cacc[i][6], cacc[i][7]);
            }
            __syncthreads();

            for (int kv = 0; kv < 64; kv += 4) {
                float4 p4[8];
                #pragma unroll
                for (int i = 0; i < 8; i++)
                    p4[i] = *(const float4*)(Ps + (ty * 8 + i) * KST + kv);
                float4 va[4], vb[4];
                #pragma unroll
                for (int tt = 0; tt < 4; tt++) {
                    va[tt] = *(const float4*)(Vs + (kv + tt) * KST + tx * 8);
                    vb[tt] = *(const float4*)(Vs + (kv + tt) * KST + tx * 8 + 4);
                }
                #pragma unroll
                for (int i = 0; i < 8; i++) {
                    const float pv[4] = {p4[i].x, p4[i].y, p4[i].z, p4[i].w};
                    #pragma unroll
                    for (int tt = 0; tt < 4; tt++) {
                        o_[i][0] += pv[tt] * va[tt].x;
                        o_[i][1] += pv[tt] * va[tt].y;
                        o_[i][2] += pv[tt] * va[tt].z;
                        o_[i][3] += pv[tt] * va[tt].w;
                        o_[i][4] += pv[tt] * vb[tt].x;
                        o_[i][5] += pv[tt] * vb[tt].y;
                        o_[i][6] += pv[tt] * vb[tt].z;
                        o_[i][7] += pv[tt] * vb[tt].w;
                    }
                }
            }
        }
    }

    #pragma unroll
    for (int i = 0; i < 8; i++) {
        const float inv = 1.0f / l_[i];
        const int grow = qr0 + ty * 8 + i;
        float* dst = ctx + ((size_t)b * Sq + grow) * Dq + h * HDq + tx * 8;
        *(float4*)(dst) = make_float4(o_[i][0] * inv, o_[i][1] * inv,
                                      o_[i][2] * inv, o_[i][3] * inv);
        *(float4*)(dst + 4) = make_float4(o_[i][4] * inv, o_[i][5] * inv,
                                          o_[i][6] * inv, o_[i][7] * inv);
    }
}

// =====================================================================
// launch
// =====================================================================
extern "C" void kernel_launch(void* const* d_in, const int* in_sizes, int n_in,
                              void* d_out, int out_size)
{
    const float* q   = (const float*)d_in[0];
    const float* k   = (const float*)d_in[1];
    const float* v   = (const float*)d_in[2];
    const int*   am  = (const int*)  d_in[3];
    const float* Wq  = (const float*)d_in[4];
    const float* Wk  = (const float*)d_in[5];
    const float* Wv  = (const float*)d_in[6];
    const float* Wo  = (const float*)d_in[7];
    const int*   mf  = (const int*)  d_in[8];
    float* out = (float*)d_out;

    float *qh, *kh, *vh, *ctx;
    cudaGetSymbolAddress((void**)&qh,  g_qh);
    cudaGetSymbolAddress((void**)&kh,  g_kh);
    cudaGetSymbolAddress((void**)&vh,  g_vh);
    cudaGetSymbolAddress((void**)&ctx, g_ctx);

    __nv_bfloat16 *qhi, *qlo, *khi, *klo, *vhi, *vlo, *chi, *clo;
    __nv_bfloat16 *wqhi, *wqlo, *wkhi, *wklo, *wvhi, *wvlo, *wohi, *wolo;
    cudaGetSymbolAddress((void**)&qhi,  g_q_hi);  cudaGetSymbolAddress((void**)&qlo,  g_q_lo);
    cudaGetSymbolAddress((void**)&khi,  g_k_hi);  cudaGetSymbolAddress((void**)&klo,  g_k_lo);
    cudaGetSymbolAddress((void**)&vhi,  g_v_hi);  cudaGetSymbolAddress((void**)&vlo,  g_v_lo);
    cudaGetSymbolAddress((void**)&chi,  g_c_hi);  cudaGetSymbolAddress((void**)&clo,  g_c_lo);
    cudaGetSymbolAddress((void**)&wqhi, g_wq_hi); cudaGetSymbolAddress((void**)&wqlo, g_wq_lo);
    cudaGetSymbolAddress((void**)&wkhi, g_wk_hi); cudaGetSymbolAddress((void**)&wklo, g_wk_lo);
    cudaGetSymbolAddress((void**)&wvhi, g_wv_hi); cudaGetSymbolAddress((void**)&wvlo, g_wv_lo);
    cudaGetSymbolAddress((void**)&wohi, g_wo_hi); cudaGetSymbolAddress((void**)&wolo, g_wo_lo);

    const int attn_smem =
        (64 * QST + 64 * KST + 64 * KST + 128 * KST) * (int)sizeof(float);
    cudaFuncSetAttribute(attn_kernel,
                         cudaFuncAttributeMaxDynamicSharedMemorySize, attn_smem);
    cudaFuncSetAttribute(gemm_mma_kernel,
                         cudaFuncAttributeMaxDynamicSharedMemorySize, GEMM_SMEM);
    cudaFuncSetAttribute(gemm_qkv_kernel,
                         cudaFuncAttributeMaxDynamicSharedMemorySize, GEMM_SMEM);

    // --- hi/lo conversions (fused) ---
    const int nIn4 = Mq * Dq / 4;
    const int nW4  = Dq * Dq / 4;
    {
        dim3 g3(nIn4 / 256, 1, 3);
        cvt_hilo3_kernel<<<g3, 256>>>(q, k, v, qhi, qlo, khi, klo, vhi, vlo, nIn4);
        dim3 g4(nW4 / 256, 1, 4);
        cvt_hilo4_kernel<<<g4, 256>>>(Wq, Wk, Wv, Wo,
                                      wqhi, wqlo, wkhi, wklo,
                                      wvhi, wvlo, wohi, wolo, nW4);
    }

    // --- Q,K,V projections fused in one launch ---
    dim3 qkv_grid(Dq / 128, Mq / 128, 3);   // (8, 32, 3) = 768 CTAs
    gemm_qkv_kernel<<<qkv_grid, 256, GEMM_SMEM>>>(
        qhi, qlo, khi, klo, vhi, vlo,
        wqhi, wqlo, wkhi, wklo, wvhi, wvlo, qh, kh, vh);

    // --- attention ---
    dim3 attn_grid(Sq / 128, Bq * Hq);
    attn_kernel<<<attn_grid, 128, attn_smem>>>(qh, kh, vh, am, mf, ctx);

    // --- output projection ---
    cvt_hilo_kernel<<<nIn4 / 256, 256>>>(ctx, chi, clo, nIn4);
    dim3 gemm_grid(Dq / 128, Mq / 128);
    gemm_mma_kernel<<<gemm_grid, 256, GEMM_SMEM>>>(chi, clo, wohi, wolo, out, 0);
}

// round 11
// speedup vs baseline: 3.7367x; 1.9934x over previous
#include <cuda_runtime.h>
#include <cuda_bf16.h>
#include <math.h>
#include <stdint.h>

// ---------------- problem constants ----------------
#define Bq   2
#define Sq   2048
#define Dq   1024
#define Hq   16
#define HDq  64
#define Mq   (Bq*Sq)          // 4096
#define NEGV (-10000.0f)

// ---------------- scratch (device globals; no allocation allowed) ----------
// bf16 hi/lo copies for tensor-core GEMMs (inputs/weights)
__device__ __nv_bfloat16 g_q_hi[Mq*Dq],  g_q_lo[Mq*Dq];
__device__ __nv_bfloat16 g_k_hi[Mq*Dq],  g_k_lo[Mq*Dq];
__device__ __nv_bfloat16 g_v_hi[Mq*Dq],  g_v_lo[Mq*Dq];
__device__ __nv_bfloat16 g_wq_hi[Dq*Dq], g_wq_lo[Dq*Dq];
__device__ __nv_bfloat16 g_wk_hi[Dq*Dq], g_wk_lo[Dq*Dq];
__device__ __nv_bfloat16 g_wv_hi[Dq*Dq], g_wv_lo[Dq*Dq];
__device__ __nv_bfloat16 g_wo_hi[Dq*Dq], g_wo_lo[Dq*Dq];
// head-split projected Q/K/V as bf16 hi/lo (written by QKV GEMM epilogue)
__device__ __nv_bfloat16 g_qhh[Bq*Hq*Sq*HDq], g_qhl[Bq*Hq*Sq*HDq];
__device__ __nv_bfloat16 g_khh[Bq*Hq*Sq*HDq], g_khl[Bq*Hq*Sq*HDq];
__device__ __nv_bfloat16 g_vhh[Bq*Hq*Sq*HDq], g_vhl[Bq*Hq*Sq*HDq];
// attention output (merged [b*S+s][D]) as bf16 hi/lo
__device__ __nv_bfloat16 g_c_hi[Mq*Dq], g_c_lo[Mq*Dq];

// =====================================================================
// helpers
// =====================================================================
__device__ __forceinline__ uint32_t smem_u32(const void* p) {
    uint32_t a;
    asm("{ .reg .u64 t; cvta.to.shared.u64 t, %1; cvt.u32.u64 %0, t; }"
        : "=r"(a) : "l"(p));
    return a;
}

__device__ __forceinline__ void ldsm_x4(uint32_t* r, uint32_t addr) {
    asm volatile("ldmatrix.sync.aligned.m8n8.x4.shared.b16 {%0,%1,%2,%3}, [%4];"
                 : "=r"(r[0]), "=r"(r[1]), "=r"(r[2]), "=r"(r[3]) : "r"(addr));
}
__device__ __forceinline__ void ldsm_x4t(uint32_t* r, uint32_t addr) {
    asm volatile("ldmatrix.sync.aligned.m8n8.x4.trans.shared.b16 {%0,%1,%2,%3}, [%4];"
                 : "=r"(r[0]), "=r"(r[1]), "=r"(r[2]), "=r"(r[3]) : "r"(addr));
}

__device__ __forceinline__ void mma_bf16(float* c, const uint32_t* a,
                                         const uint32_t* b) {
    asm volatile(
        "mma.sync.aligned.m16n8k16.row.col.f32.bf16.bf16.f32 "
        "{%0,%1,%2,%3}, {%4,%5,%6,%7}, {%8,%9}, {%0,%1,%2,%3};"
        : "+f"(c[0]), "+f"(c[1]), "+f"(c[2]), "+f"(c[3])
        : "r"(a[0]), "r"(a[1]), "r"(a[2]), "r"(a[3]), "r"(b[0]), "r"(b[1]));
}

__device__ __forceinline__ void cpasync16(uint32_t dst, const void* src) {
    asm volatile("cp.async.cg.shared.global [%0], [%1], 16;"
                 :: "r"(dst), "l"(src) : "memory");
}
#define CP_COMMIT() asm volatile("cp.async.commit_group;" ::: "memory")
#define CP_WAIT(n)  asm volatile("cp.async.wait_group %0;" :: "n"(n) : "memory")

// Fast exp for x <= 0 on FMA/ALU pipes only (validated round 10).
__device__ __forceinline__ float fexp_neg(float x) {
    x = fmaxf(x, -80.0f);
    const float y = x * 1.4426950408889634f;
    const float t = y + 12582912.0f;
    const float nf = t - 12582912.0f;
    const float f = y - nf;
    const uint32_t sbits = (__float_as_uint(t) + (127u - 0x400000u)) << 23;
    float p = 0.0013333558f;
    p = fmaf(p, f, 0.0096181291f);
    p = fmaf(p, f, 0.0555041087f);
    p = fmaf(p, f, 0.2402265069f);
    p = fmaf(p, f, 0.6931471806f);
    p = fmaf(p, f, 1.0f);
    return p * __uint_as_float(sbits);
}

// split two floats into packed bf16 hi and bf16 residual-lo words
__device__ __forceinline__ void split2(float x, float y, uint32_t& hi, uint32_t& lo) {
    __nv_bfloat16 hx = __float2bfloat16(x), hy = __float2bfloat16(y);
    hi = (uint32_t)__bfloat16_as_ushort(hx) |
         ((uint32_t)__bfloat16_as_ushort(hy) << 16);
    __nv_bfloat16 lx = __float2bfloat16(x - __bfloat162float(hx));
    __nv_bfloat16 ly = __float2bfloat16(y - __bfloat162float(hy));
    lo = (uint32_t)__bfloat16_as_ushort(lx) |
         ((uint32_t)__bfloat16_as_ushort(ly) << 16);
}

// =====================================================================
// fp32 -> bf16 hi/lo split
// =====================================================================
__device__ __forceinline__ void cvt_body(const float* __restrict__ x,
                                         __nv_bfloat16* __restrict__ hi,
                                         __nv_bfloat16* __restrict__ lo,
                                         int n4)
{
    int i = blockIdx.x * blockDim.x + threadIdx.x;
    if (i >= n4) return;
    float4 v = ((const float4*)x)[i];
    uint32_t h0, l0, h1, l1;
    split2(v.x, v.y, h0, l0);
    split2(v.z, v.w, h1, l1);
    ((uint2*)hi)[i] = make_uint2(h0, h1);
    ((uint2*)lo)[i] = make_uint2(l0, l1);
}

__global__ __launch_bounds__(256)
void cvt_hilo3_kernel(const float* x0, const float* x1, const float* x2,
                      __nv_bfloat16* h0, __nv_bfloat16* l0,
                      __nv_bfloat16* h1, __nv_bfloat16* l1,
                      __nv_bfloat16* h2, __nv_bfloat16* l2, int n4)
{
    const float* x; __nv_bfloat16 *hh, *ll;
    switch (blockIdx.z) {
        case 0:  x = x0; hh = h0; ll = l0; break;
        case 1:  x = x1; hh = h1; ll = l1; break;
        default: x = x2; hh = h2; ll = l2; break;
    }
    cvt_body(x, hh, ll, n4);
}

__global__ __launch_bounds__(256)
void cvt_hilo4_kernel(const float* x0, const float* x1, const float* x2, const float* x3,
                      __nv_bfloat16* h0, __nv_bfloat16* l0,
                      __nv_bfloat16* h1, __nv_bfloat16* l1,
                      __nv_bfloat16* h2, __nv_bfloat16* l2,
                      __nv_bfloat16* h3, __nv_bfloat16* l3, int n4)
{
    const float* x; __nv_bfloat16 *hh, *ll;
    switch (blockIdx.z) {
        case 0:  x = x0; hh = h0; ll = l0; break;
        case 1:  x = x1; hh = h1; ll = l1; break;
        case 2:  x = x2; hh = h2; ll = l2; break;
        default: x = x3; hh = h3; ll = l3; break;
    }
    cvt_body(x, hh, ll, n4);
}

// =====================================================================
// Tensor-core GEMM (validated round 9/10 body; epilogue extended):
//   C = A (MxK rm) * B^T (B NxK rm), M=4096 N=1024 K=1024.
// mode 0: fp32 C[m*N+n]
// mode 1: bf16 hi/lo head-split [(b*H+h)*S+s]*64+hd, scaled by `scale`.
// =====================================================================
#define GSTG 32768
#define GOFF_ALO 8192
#define GOFF_BHI 16384
#define GOFF_BLO 24576
#define GEMM_SMEM (3*GSTG)

__device__ __forceinline__
void gemm_body(char* gsm,
               const __nv_bfloat16* __restrict__ Ahi,
               const __nv_bfloat16* __restrict__ Alo,
               const __nv_bfloat16* __restrict__ Bhi,
               const __nv_bfloat16* __restrict__ Blo,
               float* __restrict__ C,
               __nv_bfloat16* __restrict__ Chi,
               __nv_bfloat16* __restrict__ Clo,
               float scale, int mode)
{
    const uint32_t sbase = smem_u32(gsm);

    const int tid  = threadIdx.x;
    const int wid  = tid >> 5;
    const int lane = tid & 31;
    const int m0 = blockIdx.y * 128;
    const int n0 = blockIdx.x * 128;
    const int wm0 = (wid & 1) * 64;
    const int wn0 = (wid >> 1) * 32;

    const int mt = lane >> 3;
    const int rr = lane & 7;
    const int a_row = rr + 8 * (mt & 1);
    const int a_kof = 8 * (mt >> 1);
    const int b_row = rr + 8 * (mt >> 1);
    const int b_kof = 8 * (mt & 1);

    const int ld_r0 = tid >> 2;
    const int ld_c0 = tid & 3;
    const int ld_r1 = ld_r0 + 64;

    float acc[4][4][4];
    #pragma unroll
    for (int i = 0; i < 4; i++)
        #pragma unroll
        for (int j = 0; j < 4; j++)
            #pragma unroll
            for (int e = 0; e < 4; e++) acc[i][j][e] = 0.0f;

    auto issue_stage = [&](int ch, int stg) {
        const int k0 = ch * 32;
        const uint32_t sst = sbase + stg * GSTG;
        {
            const int r = ld_r0, c = ld_c0;
            const uint32_t sw = (uint32_t)(r * 64 + ((c ^ ((r >> 1) & 3)) << 4));
            const size_t goA = (size_t)(m0 + r) * Dq + k0 + c * 8;
            const size_t goB = (size_t)(n0 + r) * Dq + k0 + c * 8;
            cpasync16(sst + sw,            Ahi + goA);
            cpasync16(sst + GOFF_ALO + sw, Alo + goA);
            cpasync16(sst + GOFF_BHI + sw, Bhi + goB);
            cpasync16(sst + GOFF_BLO + sw, Blo + goB);
        }
        {
            const int r = ld_r1, c = ld_c0;
            const uint32_t sw = (uint32_t)(r * 64 + ((c ^ ((r >> 1) & 3)) << 4));
            const size_t goA = (size_t)(m0 + r) * Dq + k0 + c * 8;
            const size_t goB = (size_t)(n0 + r) * Dq + k0 + c * 8;
            cpasync16(sst + sw,            Ahi + goA);
            cpasync16(sst + GOFF_ALO + sw, Alo + goA);
            cpasync16(sst + GOFF_BHI + sw, Bhi + goB);
            cpasync16(sst + GOFF_BLO + sw, Blo + goB);
        }
    };

    issue_stage(0, 0); CP_COMMIT();
    issue_stage(1, 1); CP_COMMIT();

    const int NCH = Dq / 32;   // 32
    for (int ch = 0; ch < NCH; ch++) {
        CP_WAIT(1);
        __syncthreads();
        if (ch + 2 < NCH) issue_stage(ch + 2, (ch + 2) % 3);
        CP_COMMIT();

        const uint32_t sst = sbase + (ch % 3) * GSTG;
        #pragma unroll
        for (int ks = 0; ks < 32; ks += 16) {
            uint32_t bhi[2][4], blo[2][4];
            #pragma unroll
            for (int p = 0; p < 2; p++) {
                const int row = wn0 + p * 16 + b_row;
                const int cch = (ks + b_kof) >> 3;
                const uint32_t ad = sst + GOFF_BHI +
                    (uint32_t)(row * 64 + ((cch ^ ((row >> 1) & 3)) << 4));
                ldsm_x4(bhi[p], ad);
                ldsm_x4(blo[p], ad + (GOFF_BLO - GOFF_BHI));
            }
            #pragma unroll
            for (int mf = 0; mf < 4; mf++) {
                const int row = wm0 + mf * 16 + a_row;
                const int cch = (ks + a_kof) >> 3;
                const uint32_t ad = sst +
                    (uint32_t)(row * 64 + ((cch ^ ((row >> 1) & 3)) << 4));
                uint32_t ahi[4], alo[4];
                ldsm_x4(ahi, ad);
                ldsm_x4(alo, ad + GOFF_ALO);
                #pragma unroll
                for (int nf = 0; nf < 4; nf++) {
                    const uint32_t* bh = &bhi[nf >> 1][(nf & 1) * 2];
                    const uint32_t* bl = &blo[nf >> 1][(nf & 1) * 2];
                    mma_bf16(acc[mf][nf], ahi, bh);
                    mma_bf16(acc[mf][nf], ahi, bl);
                    mma_bf16(acc[mf][nf], alo, bh);
                }
            }
        }
    }
    __syncthreads();

    const int g  = lane >> 2;
    const int cc = (lane & 3) * 2;
    #pragma unroll
    for (int mf = 0; mf < 4; mf++)
        #pragma unroll
        for (int nf = 0; nf < 4; nf++) {
            const int mA = m0 + wm0 + mf * 16 + g;
            const int nA = n0 + wn0 + nf * 8 + cc;
            #pragma unroll
            for (int half = 0; half < 2; half++) {
                const int m = mA + half * 8;
                const float vx = acc[mf][nf][half * 2];
                const float vy = acc[mf][nf][half * 2 + 1];
                if (mode == 0) {
                    *(float2*)(C + (size_t)m * Dq + nA) = make_float2(vx, vy);
                } else {
                    const int bb = m >> 11;
                    const int ss = m & (Sq - 1);
                    const int hh = nA >> 6;
                    const int hd = nA & 63;
                    const size_t idx =
                        ((size_t)(bb * Hq + hh) * Sq + ss) * HDq + hd;
                    uint32_t ph, pl;
                    split2(vx * scale, vy * scale, ph, pl);
                    *(uint32_t*)(Chi + idx) = ph;
                    *(uint32_t*)(Clo + idx) = pl;
                }
            }
        }
}

// Wo projection (fp32 out)
__global__ __launch_bounds__(256, 2)
void gemm_mma_kernel(const __nv_bfloat16* __restrict__ Ahi,
                     const __nv_bfloat16* __restrict__ Alo,
                     const __nv_bfloat16* __restrict__ Bhi,
                     const __nv_bfloat16* __restrict__ Blo,
                     float* __restrict__ C)
{
    extern __shared__ __align__(16) char gsm[];
    gemm_body(gsm, Ahi, Alo, Bhi, Blo, C, nullptr, nullptr, 1.0f, 0);
}

// fused QKV: blockIdx.z selects operand set; writes bf16 hi/lo head-split.
// Q gets the 1/8 softmax scale folded in (exact power of two).
__global__ __launch_bounds__(256, 2)
void gemm_qkv_kernel(const __nv_bfloat16* qhi, const __nv_bfloat16* qlo,
                     const __nv_bfloat16* khi, const __nv_bfloat16* klo,
                     const __nv_bfloat16* vhi, const __nv_bfloat16* vlo,
                     const __nv_bfloat16* wqhi, const __nv_bfloat16* wqlo,
                     const __nv_bfloat16* wkhi, const __nv_bfloat16* wklo,
                     const __nv_bfloat16* wvhi, const __nv_bfloat16* wvlo,
                     __nv_bfloat16* qhh, __nv_bfloat16* qhl,
                     __nv_bfloat16* khh, __nv_bfloat16* khl,
                     __nv_bfloat16* vhh, __nv_bfloat16* vhl)
{
    extern __shared__ __align__(16) char gsm[];
    const __nv_bfloat16 *Ah, *Al, *Bh, *Bl;
    __nv_bfloat16 *Ch, *Cl;
    float scale;
    switch (blockIdx.z) {
        case 0:  Ah=qhi; Al=qlo; Bh=wqhi; Bl=wqlo; Ch=qhh; Cl=qhl; scale=0.125f; break;
        case 1:  Ah=khi; Al=klo; Bh=wkhi; Bl=wklo; Ch=khh; Cl=khl; scale=1.0f;   break;
        default: Ah=vhi; Al=vlo; Bh=wvhi; Bl=wvlo; Ch=vhh; Cl=vhl; scale=1.0f;   break;
    }
    gemm_body(gsm, Ah, Al, Bh, Bl, nullptr, Ch, Cl, scale, 1);
}

// =====================================================================
// Tensor-core flash attention (FA2-style, hi/lo 3-pass).
// CTA = one (b,h) x 128 q rows; 8 warps, each owns one m16 q-tile.
// KV tiles of 64; K via ldmatrix (natural [kv][hd] = [n][k]); V via
// ldmatrix.trans (natural [kv][hd] = [k][n]); P fragment built in regs
// from the S accumulator. cp.async 3-stage KV pipeline.
// smem row = 64 bf16 = 128B = 8x16B chunks; swizzle: chunk ^= (row & 7).
// Exact reference masking + conditional tail phase preserved.
// =====================================================================
#define AOFF_QLO 16384
#define AOFF_KV  32768
#define AKV_STG  32768
#define AOFF_KLO 8192
#define AOFF_VHI 16384
#define AOFF_VLO 24576
#define AOFF_PAD 131072
#define ATT_SMEM 139264

__global__ __launch_bounds__(256, 1)
void attn_kernel(const __nv_bfloat16* __restrict__ qhh, const __nv_bfloat16* __restrict__ qhl,
                 const __nv_bfloat16* __restrict__ khh, const __nv_bfloat16* __restrict__ khl,
                 const __nv_bfloat16* __restrict__ vhh, const __nv_bfloat16* __restrict__ vhl,
                 const int* __restrict__ attn_mask,
                 const int* __restrict__ mask_future_p,
                 __nv_bfloat16* __restrict__ chi, __nv_bfloat16* __restrict__ clo)
{
    extern __shared__ __align__(16) char smemb[];
    const uint32_t sb = smem_u32(smemb);
    __shared__ float wred[8];
    __shared__ int s_needtail;

    const int tid  = threadIdx.x;
    const int wid  = tid >> 5;            // 0..7 : one m16 tile each
    const int lane = tid & 31;
    const int bh = blockIdx.y;            // b*H + h
    const int b  = bh >> 4;
    const int h  = bh & 15;
    const int qb = blockIdx.x;            // 0..15
    const int qr0 = qb * 128;
    const int g  = lane >> 2;             // row within 8
    const int qd = lane & 3;              // col quad
    const int mt = lane >> 3;             // ldmatrix matrix id
    const int rr = lane & 7;
    const int mask_future = mask_future_p[0];

    // --- Q tiles + pad mask: one cp.async group ---
    {
        #pragma unroll
        for (int j = 0; j < 8; j++) {
            const int idx = tid + j * 256;          // 0..2047
            const int sel = idx >> 10;              // 0 hi / 1 lo
            const int e = idx & 1023;
            const int r = e >> 3, c = e & 7;
            const __nv_bfloat16* src = (sel ? qhl : qhh) +
                ((size_t)bh * Sq + qr0 + r) * HDq + c * 8;
            cpasync16(sb + sel * 16384 + r * 128 + ((c ^ (r & 7)) << 4), src);
        }
        #pragma unroll
        for (int k2 = 0; k2 < 2; k2++) {
            const int chunk = tid + k2 * 256;       // 0..511
            cpasync16(sb + AOFF_PAD + chunk * 16,
                      attn_mask + (size_t)b * Sq + chunk * 4);
        }
        CP_COMMIT();
    }
    const int* padsm = (const int*)(smemb + AOFF_PAD);

    float m_[2] = {-1e30f, -1e30f};
    float l_[2] = {0.0f, 0.0f};
    float Of[8][4];
    #pragma unroll
    for (int j = 0; j < 8; j++)
        #pragma unroll
        for (int e = 0; e < 4; e++) Of[j][e] = 0.0f;
    uint32_t qfh[4][4], qfl[4][4];
    bool qloaded = false;

    auto issue_kv = [&](int t, int s) {
        const int kv0 = t * 64;
        const uint32_t dst0 = sb + AOFF_KV + s * AKV_STG;
        #pragma unroll
        for (int j = 0; j < 8; j++) {
            const int idx = tid + j * 256;          // 0..2047
            const int arr = idx >> 9;               // 0 khi,1 klo,2 vhi,3 vlo
            const int e = idx & 511;
            const int r = e >> 3, c = e & 7;
            const __nv_bfloat16* base =
                (arr == 0) ? khh : (arr == 1) ? khl : (arr == 2) ? vhh : vhl;
            const __nv_bfloat16* src = base + ((size_t)bh * Sq + kv0 + r) * HDq + c * 8;
            cpasync16(dst0 + arr * 8192 + r * 128 + ((c ^ (r & 7)) << 4), src);
        }
    };

    const int ntiles = Sq / 64;                       // 32
    const int limit = mask_future ? (2 * qb + 2) : ntiles;

    for (int phase = 0; phase < 2; phase++) {
        int t0, t1;
        if (phase == 0) { t0 = 0; t1 = limit; }
        else {
            if (!mask_future || limit >= ntiles) break;
            float mymin = fminf(m_[0], m_[1]);
            #pragma unroll
            for (int off = 16; off > 0; off >>= 1)
                mymin = fminf(mymin, __shfl_xor_sync(0xffffffffu, mymin, off));
            __syncthreads();
            if (lane == 0) wred[wid] = mymin;
            __syncthreads();
            if (tid == 0) {
                float mn = wred[0];
                #pragma unroll
                for (int w = 1; w < 8; w++) mn = fminf(mn, wred[w]);
                s_needtail = (mn < -5000.0f) ? 1 : 0;
            }
            __syncthreads();
            if (!s_needtail) break;
            t0 = limit; t1 = ntiles;
        }

        issue_kv(t0, 0); CP_COMMIT();
        if (t0 + 1 < t1) issue_kv(t0 + 1, 1);
        CP_COMMIT();

        for (int i = t0; i < t1; i++) {
            CP_WAIT(1);
            __syncthreads();
            if (!qloaded) {
                #pragma unroll
                for (int ks = 0; ks < 4; ks++) {
                    const int qrow = wid * 16 + rr + 8 * (mt & 1);
                    const int kch = 2 * ks + (mt >> 1);
                    const uint32_t ad = sb + qrow * 128 + ((kch ^ (qrow & 7)) << 4);
                    ldsm_x4(qfh[ks], ad);
                    ldsm_x4(qfl[ks], ad + AOFF_QLO);
                }
                qloaded = true;
            }
            if (i + 2 < t1) issue_kv(i + 2, (i - t0 + 2) % 3);
            CP_COMMIT();

            const uint32_t kb = sb + AOFF_KV + ((i - t0) % 3) * AKV_STG;
            const int kv0 = i * 64;

            // ---- S = Q K^T (hi/lo 3-pass), fp32 accum ----
            float cacc[8][4];
            #pragma unroll
            for (int j = 0; j < 8; j++)
                #pragma unroll
                for (int e = 0; e < 4; e++) cacc[j][e] = 0.0f;

            #pragma unroll
            for (int ks = 0; ks < 4; ks++) {
                #pragma unroll
                for (int np = 0; np < 4; np++) {
                    const int brow = np * 16 + rr + 8 * (mt >> 1);
                    const int kch = 2 * ks + (mt & 1);
                    const uint32_t ad = kb + brow * 128 + ((kch ^ (brow & 7)) << 4);
                    uint32_t k4h[4], k4l[4];
                    ldsm_x4(k4h, ad);
                    ldsm_x4(k4l, ad + AOFF_KLO);
                    mma_bf16(cacc[2*np],   qfh[ks], &k4h[0]);
                    mma_bf16(cacc[2*np],   qfh[ks], &k4l[0]);
                    mma_bf16(cacc[2*np],   qfl[ks], &k4h[0]);
                    mma_bf16(cacc[2*np+1], qfh[ks], &k4h[2]);
                    mma_bf16(cacc[2*np+1], qfh[ks], &k4l[2]);
                    mma_bf16(cacc[2*np+1], qfl[ks], &k4h[2]);
                }
            }

            // ---- mask (causal add then pad replace; exact ref order) ----
            const int row0 = qr0 + wid * 16 + g;
            const int row1 = row0 + 8;
            #pragma unroll
            for (int j = 0; j < 8; j++) {
                const int col0 = kv0 + 8 * j + 2 * qd;
                float s0 = cacc[j][0], s1 = cacc[j][1];
                float s2 = cacc[j][2], s3 = cacc[j][3];
                if (mask_future) {
                    if (col0 > row0)     s0 += NEGV;
                    if (col0 + 1 > row0) s1 += NEGV;
                    if (col0 > row1)     s2 += NEGV;
                    if (col0 + 1 > row1) s3 += NEGV;
                }
                const int pa = padsm[col0], pb = padsm[col0 + 1];
                if (pa == 0) { s0 = NEGV; s2 = NEGV; }
                if (pb == 0) { s1 = NEGV; s3 = NEGV; }
                cacc[j][0] = s0; cacc[j][1] = s1;
                cacc[j][2] = s2; cacc[j][3] = s3;
            }

            // ---- online softmax ----
            float mx0 = -1e30f, mx1 = -1e30f;
            #pragma unroll
            for (int j = 0; j < 8; j++) {
                mx0 = fmaxf(mx0, fmaxf(cacc[j][0], cacc[j][1]));
                mx1 = fmaxf(mx1, fmaxf(cacc[j][2], cacc[j][3]));
            }
            #pragma unroll
            for (int off = 1; off <= 2; off <<= 1) {
                mx0 = fmaxf(mx0, __shfl_xor_sync(0xffffffffu, mx0, off));
                mx1 = fmaxf(mx1, __shfl_xor_sync(0xffffffffu, mx1, off));
            }
            const float mn0 = fmaxf(m_[0], mx0);
            const float mn1 = fmaxf(m_[1], mx1);
            const float al0 = fexp_neg(m_[0] - mn0);
            const float al1 = fexp_neg(m_[1] - mn1);
            float rs0 = 0.0f, rs1 = 0.0f;
            #pragma unroll
            for (int j = 0; j < 8; j++) {
                const float p0 = fexp_neg(cacc[j][0] - mn0);
                const float p1 = fexp_neg(cacc[j][1] - mn0);
                const float p2 = fexp_neg(cacc[j][2] - mn1);
                const float p3 = fexp_neg(cacc[j][3] - mn1);
                cacc[j][0] = p0; cacc[j][1] = p1;
                cacc[j][2] = p2; cacc[j][3] = p3;
                rs0 += p0 + p1; rs1 += p2 + p3;
            }
            #pragma unroll
            for (int off = 1; off <= 2; off <<= 1) {
                rs0 += __shfl_xor_sync(0xffffffffu, rs0, off);
                rs1 += __shfl_xor_sync(0xffffffffu, rs1, off);
            }
            l_[0] = l_[0] * al0 + rs0;  m_[0] = mn0;
            l_[1] = l_[1] * al1 + rs1;  m_[1] = mn1;
            #pragma unroll
            for (int j = 0; j < 8; j++) {
                Of[j][0] *= al0; Of[j][1] *= al0;
                Of[j][2] *= al1; Of[j][3] *= al1;
            }

            // ---- O += P V (hi/lo 3-pass); P frag from S accumulator ----
            const uint32_t vb = kb + AOFF_VHI;
            #pragma unroll
            for (int ks = 0; ks < 4; ks++) {
                uint32_t pah[4], pal[4];
                split2(cacc[2*ks][0],   cacc[2*ks][1],   pah[0], pal[0]);
                split2(cacc[2*ks][2],   cacc[2*ks][3],   pah[1], pal[1]);
                split2(cacc[2*ks+1][0], cacc[2*ks+1][1], pah[2], pal[2]);
                split2(cacc[2*ks+1][2], cacc[2*ks+1][3], pah[3], pal[3]);
                #pragma unroll
                for (int np = 0; np < 4; np++) {
                    const int kvr = ks * 16 + rr + 8 * (mt & 1);
                    const int nch = 2 * np + (mt >> 1);
                    const uint32_t ad = vb + kvr * 128 + ((nch ^ (kvr & 7)) << 4);
                    uint32_t v4h[4], v4l[4];
                    ldsm_x4t(v4h, ad);
                    ldsm_x4t(v4l, ad + (AOFF_VLO - AOFF_VHI));
                    mma_bf16(Of[2*np],   pah, &v4h[0]);
                    mma_bf16(Of[2*np],   pah, &v4l[0]);
                    mma_bf16(Of[2*np],   pal, &v4h[0]);
                    mma_bf16(Of[2*np+1], pah, &v4h[2]);
                    mma_bf16(Of[2*np+1], pah, &v4l[2]);
                    mma_bf16(Of[2*np+1], pal, &v4h[2]);
                }
            }
        }
    }

    // ---- epilogue: normalize, write ctx hi/lo bf16 ----
    const float inv0 = 1.0f / l_[0];
    const float inv1 = 1.0f / l_[1];
    const int row0 = qr0 + wid * 16 + g;
    const int row1 = row0 + 8;
    #pragma unroll
    for (int jo = 0; jo < 8; jo++) {
        const int col = h * HDq + 8 * jo + 2 * qd;
        const size_t i0 = ((size_t)b * Sq + row0) * Dq + col;
        const size_t i1 = ((size_t)b * Sq + row1) * Dq + col;
        uint32_t ph, pl;
        split2(Of[jo][0] * inv0, Of[jo][1] * inv0, ph, pl);
        *(uint32_t*)(chi + i0) = ph;
        *(uint32_t*)(clo + i0) = pl;
        split2(Of[jo][2] * inv1, Of[jo][3] * inv1, ph, pl);
        *(uint32_t*)(chi + i1) = ph;
        *(uint32_t*)(clo + i1) = pl;
    }
}

// =====================================================================
// launch
// =====================================================================
extern "C" void kernel_launch(void* const* d_in, const int* in_sizes, int n_in,
                              void* d_out, int out_size)
{
    const float* q   = (const float*)d_in[0];
    const float* k   = (const float*)d_in[1];
    const float* v   = (const float*)d_in[2];
    const int*   am  = (const int*)  d_in[3];
    const float* Wq  = (const float*)d_in[4];
    const float* Wk  = (const float*)d_in[5];
    const float* Wv  = (const float*)d_in[6];
    const float* Wo  = (const float*)d_in[7];
    const int*   mf  = (const int*)  d_in[8];
    float* out = (float*)d_out;

    __nv_bfloat16 *qhi, *qlo, *khi, *klo, *vhi, *vlo;
    __nv_bfloat16 *wqhi, *wqlo, *wkhi, *wklo, *wvhi, *wvlo, *wohi, *wolo;
    __nv_bfloat16 *qhh, *qhl, *khh, *khl, *vhh, *vhl, *chi, *clo;
    cudaGetSymbolAddress((void**)&qhi,  g_q_hi);  cudaGetSymbolAddress((void**)&qlo,  g_q_lo);
    cudaGetSymbolAddress((void**)&khi,  g_k_hi);  cudaGetSymbolAddress((void**)&klo,  g_k_lo);
    cudaGetSymbolAddress((void**)&vhi,  g_v_hi);  cudaGetSymbolAddress((void**)&vlo,  g_v_lo);
    cudaGetSymbolAddress((void**)&wqhi, g_wq_hi); cudaGetSymbolAddress((void**)&wqlo, g_wq_lo);
    cudaGetSymbolAddress((void**)&wkhi, g_wk_hi); cudaGetSymbolAddress((void**)&wklo, g_wk_lo);
    cudaGetSymbolAddress((void**)&wvhi, g_wv_hi); cudaGetSymbolAddress((void**)&wvlo, g_wv_lo);
    cudaGetSymbolAddress((void**)&wohi, g_wo_hi); cudaGetSymbolAddress((void**)&wolo, g_wo_lo);
    cudaGetSymbolAddress((void**)&qhh,  g_qhh);   cudaGetSymbolAddress((void**)&qhl,  g_qhl);
    cudaGetSymbolAddress((void**)&khh,  g_khh);   cudaGetSymbolAddress((void**)&khl,  g_khl);
    cudaGetSymbolAddress((void**)&vhh,  g_vhh);   cudaGetSymbolAddress((void**)&vhl,  g_vhl);
    cudaGetSymbolAddress((void**)&chi,  g_c_hi);  cudaGetSymbolAddress((void**)&clo,  g_c_lo);

    cudaFuncSetAttribute(gemm_mma_kernel,
                         cudaFuncAttributeMaxDynamicSharedMemorySize, GEMM_SMEM);
    cudaFuncSetAttribute(gemm_qkv_kernel,
                         cudaFuncAttributeMaxDynamicSharedMemorySize, GEMM_SMEM);
    cudaFuncSetAttribute(attn_kernel,
                         cudaFuncAttributeMaxDynamicSharedMemorySize, ATT_SMEM);

    // 1) hi/lo conversions
    const int nIn4 = Mq * Dq / 4;
    const int nW4  = Dq * Dq / 4;
    {
        dim3 g3(nIn4 / 256, 1, 3);
        cvt_hilo3_kernel<<<g3, 256>>>(q, k, v, qhi, qlo, khi, klo, vhi, vlo, nIn4);
        dim3 g4(nW4 / 256, 1, 4);
        cvt_hilo4_kernel<<<g4, 256>>>(Wq, Wk, Wv, Wo,
                                      wqhi, wqlo, wkhi, wklo,
                                      wvhi, wvlo, wohi, wolo, nW4);
    }

    // 2) fused QKV projections -> bf16 hi/lo head-split (Q pre-scaled 1/8)
    dim3 qkv_grid(Dq / 128, Mq / 128, 3);
    gemm_qkv_kernel<<<qkv_grid, 256, GEMM_SMEM>>>(
        qhi, qlo, khi, klo, vhi, vlo,
        wqhi, wqlo, wkhi, wklo, wvhi, wvlo,
        qhh, qhl, khh, khl, vhh, vhl);

    // 3) tensor-core flash attention -> ctx hi/lo bf16
    dim3 attn_grid(Sq / 128, Bq * Hq);
    attn_kernel<<<attn_grid, 256, ATT_SMEM>>>(
        qhh, qhl, khh, khl, vhh, vhl, am, mf, chi, clo);

    // 4) output projection
    dim3 gemm_grid(Dq / 128, Mq / 128);
    gemm_mma_kernel<<<gemm_grid, 256, GEMM_SMEM>>>(chi, clo, wohi, wolo, out);
}